// round 1
// baseline (speedup 1.0000x reference)
#include <cuda_runtime.h>

#define HID 256
#define NH 4
#define DH 64
#define N_MOLS 2048
#define MAX_LEN 128
#define MAX_TOTAL (1 + N_MOLS * MAX_LEN)

// Scratch (device globals: allocation-free rule)
__device__ float g_Q[(size_t)MAX_TOTAL * HID];
__device__ float g_K[(size_t)MAX_TOTAL * HID];
__device__ float g_V[(size_t)MAX_TOTAL * HID];
__device__ float g_O[(size_t)MAX_TOTAL * HID];

// ---------------------------------------------------------------------------
// Kernel A: Q/K/V = message @ W{q,k,v}^T   (torch Linear: y[r][c] = sum_k x[r][k]*W[c][k])
// BM=128, BN=64, BK=16; 256 threads; 8x4 micro-tile.
// blockIdx.y in [0,12): mat = y>>2 selects Wq/Wk/Wv, (y&3)*64 = col tile.
// ---------------------------------------------------------------------------
__global__ void qkv_kernel(const float* __restrict__ msg,
                           const float* __restrict__ Wq,
                           const float* __restrict__ Wk,
                           const float* __restrict__ Wv,
                           int total) {
    const int mat  = blockIdx.y >> 2;
    const int col0 = (blockIdx.y & 3) * 64;
    const float* __restrict__ W = (mat == 0) ? Wq : (mat == 1 ? Wk : Wv);
    float* __restrict__ Out = (mat == 0) ? g_Q : (mat == 1 ? g_K : g_V);
    const int row0 = blockIdx.x * 128;

    __shared__ float Xs[16][128];
    __shared__ float Ws[16][64];

    const int tid = threadIdx.x;           // 256 threads
    const int tm = (tid & 15) * 8;         // 0..120
    const int tn = (tid >> 4) * 4;         // 0..60

    float acc[8][4];
#pragma unroll
    for (int i = 0; i < 8; i++)
#pragma unroll
        for (int j = 0; j < 4; j++) acc[i][j] = 0.f;

    const int lm = tid >> 1;               // X-load row 0..127
    const int lk = (tid & 1) * 8;          // X-load k offset
    const int wn = tid >> 2;               // W-load out-col 0..63
    const int wk = (tid & 3) * 4;          // W-load k offset

    for (int kb = 0; kb < HID; kb += 16) {
        // load X tile (transposed into Xs[k][m])
        {
            int grow = row0 + lm;
            float4 v0, v1;
            if (grow < total) {
                const float* p = msg + (size_t)grow * HID + kb + lk;
                v0 = *(const float4*)p;
                v1 = *(const float4*)(p + 4);
            } else {
                v0 = make_float4(0.f, 0.f, 0.f, 0.f);
                v1 = v0;
            }
            Xs[lk + 0][lm] = v0.x; Xs[lk + 1][lm] = v0.y;
            Xs[lk + 2][lm] = v0.z; Xs[lk + 3][lm] = v0.w;
            Xs[lk + 4][lm] = v1.x; Xs[lk + 5][lm] = v1.y;
            Xs[lk + 6][lm] = v1.z; Xs[lk + 7][lm] = v1.w;
        }
        // load W tile (Ws[k][n])
        {
            const float* p = W + (size_t)(col0 + wn) * HID + kb + wk;
            float4 v = *(const float4*)p;
            Ws[wk + 0][wn] = v.x; Ws[wk + 1][wn] = v.y;
            Ws[wk + 2][wn] = v.z; Ws[wk + 3][wn] = v.w;
        }
        __syncthreads();
#pragma unroll
        for (int k = 0; k < 16; k++) {
            float a[8], b[4];
#pragma unroll
            for (int i = 0; i < 8; i++) a[i] = Xs[k][tm + i];
#pragma unroll
            for (int j = 0; j < 4; j++) b[j] = Ws[k][tn + j];
#pragma unroll
            for (int i = 0; i < 8; i++)
#pragma unroll
                for (int j = 0; j < 4; j++)
                    acc[i][j] = fmaf(a[i], b[j], acc[i][j]);
        }
        __syncthreads();
    }

#pragma unroll
    for (int i = 0; i < 8; i++) {
        int grow = row0 + tm + i;
        if (grow < total) {
            float4 v = make_float4(acc[i][0], acc[i][1], acc[i][2], acc[i][3]);
            *(float4*)(Out + (size_t)grow * HID + col0 + tn) = v;
        }
    }
}

// ---------------------------------------------------------------------------
// Kernel B: per-(molecule, head) exact softmax attention + ReLU.
// 128 threads; thread j owns query row j. K/V tiles + score rows in dyn smem.
// ---------------------------------------------------------------------------
#define ATTN_SMEM ((2 * 128 * 64 + 128 * 129) * 4)

__global__ void attn_kernel(const int* __restrict__ b_starts,
                            const int* __restrict__ b_sizes) {
    extern __shared__ float sm[];
    float* kS = sm;                  // [128][64]
    float* vS = sm + 128 * 64;       // [128][64]
    float* sc = sm + 2 * 128 * 64;   // [128][129] (padded rows)

    const int m = blockIdx.x;
    const int h = blockIdx.y;
    const int S = b_sizes[m];
    const int start = b_starts[m];
    const int tid = threadIdx.x;     // 128 threads

    for (int idx = tid; idx < S * DH; idx += 128) {
        int i = idx >> 6, d = idx & 63;
        size_t g = (size_t)(start + i) * HID + h * DH + d;
        kS[idx] = g_K[g];
        vS[idx] = g_V[g];
    }
    __syncthreads();

    if (tid < S) {
        float4 q[16];
        const float* qp = g_Q + (size_t)(start + tid) * HID + h * DH;
#pragma unroll
        for (int d = 0; d < 16; d++) q[d] = *(const float4*)(qp + d * 4);

        float* myrow = sc + tid * 129;
        float mx = -3.4e38f;
        for (int i = 0; i < S; i++) {
            const float4* kp = (const float4*)(kS + i * DH);
            float s = 0.f;
#pragma unroll
            for (int d = 0; d < 16; d++) {
                float4 kv = kp[d];
                s = fmaf(q[d].x, kv.x, s);
                s = fmaf(q[d].y, kv.y, s);
                s = fmaf(q[d].z, kv.z, s);
                s = fmaf(q[d].w, kv.w, s);
            }
            s *= 0.125f;  // DH^-0.5
            myrow[i] = s;
            mx = fmaxf(mx, s);
        }
        float l = 0.f;
        for (int i = 0; i < S; i++) {
            float e = __expf(myrow[i] - mx);
            myrow[i] = e;
            l += e;
        }
        float inv = 1.0f / l;

        float o[DH];
#pragma unroll
        for (int d = 0; d < DH; d++) o[d] = 0.f;
        for (int i = 0; i < S; i++) {
            float p = myrow[i];
            const float4* vp = (const float4*)(vS + i * DH);
#pragma unroll
            for (int d = 0; d < 16; d++) {
                float4 vv = vp[d];
                o[d * 4 + 0] = fmaf(p, vv.x, o[d * 4 + 0]);
                o[d * 4 + 1] = fmaf(p, vv.y, o[d * 4 + 1]);
                o[d * 4 + 2] = fmaf(p, vv.z, o[d * 4 + 2]);
                o[d * 4 + 3] = fmaf(p, vv.w, o[d * 4 + 3]);
            }
        }
        float* op = g_O + (size_t)(start + tid) * HID + h * DH;
#pragma unroll
        for (int d = 0; d < DH; d += 4) {
            float4 v = make_float4(fmaxf(o[d + 0] * inv, 0.f),
                                   fmaxf(o[d + 1] * inv, 0.f),
                                   fmaxf(o[d + 2] * inv, 0.f),
                                   fmaxf(o[d + 3] * inv, 0.f));
            *(float4*)(op + d) = v;
        }
    }
}

// ---------------------------------------------------------------------------
// Kernel C: out = LayerNorm(O @ Wo^T + bo); out[0,:] = 0.
// 32 rows/CTA; full 256 cols computed into smem, then warp-per-row LN.
// ---------------------------------------------------------------------------
#define PROJ_SMEM ((2 * 32 * 257 + 16 * 64) * 4)

__global__ void proj_ln_kernel(const float* __restrict__ Wo,
                               const float* __restrict__ bo,
                               const float* __restrict__ gamma,
                               const float* __restrict__ beta,
                               float* __restrict__ out,
                               int total) {
    extern __shared__ float smc[];
    float* Xall = smc;                 // [32][257]
    float* ys   = smc + 32 * 257;      // [32][257]
    float* Ws   = smc + 2 * 32 * 257;  // [16][64]

    const int row0 = blockIdx.x * 32;
    const int tid = threadIdx.x;       // 256 threads

    for (int idx = tid; idx < 32 * HID; idx += 256) {
        int r = idx >> 8, c = idx & 255;
        int grow = row0 + r;
        Xall[r * 257 + c] = (grow < total) ? g_O[(size_t)grow * HID + c] : 0.f;
    }
    __syncthreads();

    const int tm = (tid & 15) * 2;
    const int tn = (tid >> 4) * 4;
    const int wn = tid >> 2;
    const int wk = (tid & 3) * 4;

    for (int ct = 0; ct < 4; ct++) {
        int col0 = ct * 64;
        float acc[2][4];
#pragma unroll
        for (int i = 0; i < 2; i++)
#pragma unroll
            for (int j = 0; j < 4; j++) acc[i][j] = 0.f;

        for (int kb = 0; kb < HID; kb += 16) {
            {
                const float* p = Wo + (size_t)(col0 + wn) * HID + kb + wk;
                float4 v = *(const float4*)p;
                Ws[(wk + 0) * 64 + wn] = v.x; Ws[(wk + 1) * 64 + wn] = v.y;
                Ws[(wk + 2) * 64 + wn] = v.z; Ws[(wk + 3) * 64 + wn] = v.w;
            }
            __syncthreads();
#pragma unroll
            for (int k = 0; k < 16; k++) {
                float b[4];
#pragma unroll
                for (int j = 0; j < 4; j++) b[j] = Ws[k * 64 + tn + j];
                float a0 = Xall[(tm + 0) * 257 + kb + k];
                float a1 = Xall[(tm + 1) * 257 + kb + k];
#pragma unroll
                for (int j = 0; j < 4; j++) {
                    acc[0][j] = fmaf(a0, b[j], acc[0][j]);
                    acc[1][j] = fmaf(a1, b[j], acc[1][j]);
                }
            }
            __syncthreads();
        }
#pragma unroll
        for (int i = 0; i < 2; i++)
#pragma unroll
            for (int j = 0; j < 4; j++)
                ys[(tm + i) * 257 + col0 + tn + j] = acc[i][j] + bo[col0 + tn + j];
    }
    __syncthreads();

    // LayerNorm: 8 warps, each handles 4 rows
    const int warp = tid >> 5, lane = tid & 31;
    for (int r = warp; r < 32; r += 8) {
        int grow = row0 + r;
        float v[8];
        float s = 0.f;
#pragma unroll
        for (int j = 0; j < 8; j++) {
            v[j] = ys[r * 257 + lane + j * 32];
            s += v[j];
        }
#pragma unroll
        for (int off = 16; off > 0; off >>= 1) s += __shfl_xor_sync(0xffffffffu, s, off);
        float mu = s * (1.f / 256.f);
        float qv = 0.f;
#pragma unroll
        for (int j = 0; j < 8; j++) {
            float d = v[j] - mu;
            qv += d * d;
        }
#pragma unroll
        for (int off = 16; off > 0; off >>= 1) qv += __shfl_xor_sync(0xffffffffu, qv, off);
        float rsig = rsqrtf(qv * (1.f / 256.f) + 1e-5f);
        if (grow < total) {
            bool zero_row = (grow == 0);
#pragma unroll
            for (int j = 0; j < 8; j++) {
                int c = lane + j * 32;
                float val = zero_row ? 0.f
                                     : ((v[j] - mu) * rsig * gamma[c] + beta[c]);
                out[(size_t)grow * HID + c] = val;
            }
        }
    }
}

// ---------------------------------------------------------------------------
extern "C" void kernel_launch(void* const* d_in, const int* in_sizes, int n_in,
                              void* d_out, int out_size) {
    const float* msg      = (const float*)d_in[0];
    const float* Wq       = (const float*)d_in[1];
    const float* Wk       = (const float*)d_in[2];
    const float* Wv       = (const float*)d_in[3];
    const float* Wo       = (const float*)d_in[4];
    const float* bo       = (const float*)d_in[5];
    const float* gamma    = (const float*)d_in[6];
    const float* beta     = (const float*)d_in[7];
    const int*   b_starts = (const int*)d_in[8];
    const int*   b_sizes  = (const int*)d_in[9];
    float* out = (float*)d_out;

    const int total = in_sizes[0] / HID;

    cudaFuncSetAttribute(attn_kernel,
                         cudaFuncAttributeMaxDynamicSharedMemorySize, ATTN_SMEM);
    cudaFuncSetAttribute(proj_ln_kernel,
                         cudaFuncAttributeMaxDynamicSharedMemorySize, PROJ_SMEM);

    dim3 ga((total + 127) / 128, 12);
    qkv_kernel<<<ga, 256>>>(msg, Wq, Wk, Wv, total);

    dim3 gb(N_MOLS, NH);
    attn_kernel<<<gb, 128, ATTN_SMEM>>>(b_starts, b_sizes);

    proj_ln_kernel<<<(total + 31) / 32, 256, PROJ_SMEM>>>(Wo, bo, gamma, beta, out, total);
}

// round 3
// speedup vs baseline: 1.9922x; 1.9922x over previous
#include <cuda_runtime.h>

#define HID 256
#define NH 4
#define DH 64
#define N_MOLS 2048
#define MAX_LEN 128
#define MAX_TOTAL (1 + N_MOLS * MAX_LEN)

typedef unsigned long long ull;

// Scratch (device globals: allocation-free rule)
__device__ float g_Q[(size_t)MAX_TOTAL * HID];
__device__ float g_K[(size_t)MAX_TOTAL * HID];
__device__ float g_V[(size_t)MAX_TOTAL * HID];
__device__ float g_O[(size_t)MAX_TOTAL * HID];
__device__ float g_Y[(size_t)MAX_TOTAL * HID];

// ---- packed f32x2 helpers (FFMA2 path, sm_100+) ----
__device__ __forceinline__ ull pack2(float x) {
    ull d; unsigned u = __float_as_uint(x);
    asm("mov.b64 %0, {%1, %1};" : "=l"(d) : "r"(u));
    return d;
}
__device__ __forceinline__ float2 unpack2(ull v) {
    unsigned lo, hi;
    asm("mov.b64 {%0, %1}, %2;" : "=r"(lo), "=r"(hi) : "l"(v));
    return make_float2(__uint_as_float(lo), __uint_as_float(hi));
}
__device__ __forceinline__ ull fma2(ull a, ull b, ull c) {
    ull d;
    asm("fma.rn.f32x2 %0, %1, %2, %3;" : "=l"(d) : "l"(a), "l"(b), "l"(c));
    return d;
}
__device__ __forceinline__ ull mul2(ull a, ull b) {
    ull d;
    asm("mul.rn.f32x2 %0, %1, %2;" : "=l"(d) : "l"(a), "l"(b));
    return d;
}

__device__ __forceinline__ void ld8_guard(const float* p, bool ok,
                                          float4& v0, float4& v1) {
    if (ok) {
        v0 = *(const float4*)p;
        v1 = *(const float4*)(p + 4);
    } else {
        v0 = make_float4(0.f, 0.f, 0.f, 0.f);
        v1 = v0;
    }
}

// ---------------------------------------------------------------------------
// 128x128 fp32 GEMM tile: Out[r][c] = sum_k X[r][k]*W[c][k] (+bias), FFMA2.
// 256 threads, 8x8 micro-tile (n packed into f32x2), BK=16, reg double-buffer.
// ---------------------------------------------------------------------------
__device__ __forceinline__ void gemm128(const float* __restrict__ X,
                                        const float* __restrict__ W,
                                        float* __restrict__ Out,
                                        const float* __restrict__ bias,
                                        int total, int row0, int col0) {
    __shared__ float Xs[16][132];
    __shared__ float Ws[16][132];

    const int tid = threadIdx.x;
    const int tm = (tid & 15) * 8;
    const int tn = (tid >> 4) * 8;
    const int lrow = tid >> 1;           // 0..127 (row of X / out-col of W)
    const int lk = (tid & 1) * 8;        // 0 or 8

    ull acc[8][4];
#pragma unroll
    for (int i = 0; i < 8; i++)
#pragma unroll
        for (int j = 0; j < 4; j++) acc[i][j] = 0ull;

    const bool xok = (row0 + lrow) < total;
    const float* xbase = X + (size_t)(row0 + lrow) * HID + lk;
    const float* wbase = W + (size_t)(col0 + lrow) * HID + lk;

    float4 xa0, xa1, wa0, wa1;
    ld8_guard(xbase, xok, xa0, xa1);
    wa0 = *(const float4*)wbase;
    wa1 = *(const float4*)(wbase + 4);

    for (int kb = 0; kb < HID; kb += 16) {
        Xs[lk + 0][lrow] = xa0.x; Xs[lk + 1][lrow] = xa0.y;
        Xs[lk + 2][lrow] = xa0.z; Xs[lk + 3][lrow] = xa0.w;
        Xs[lk + 4][lrow] = xa1.x; Xs[lk + 5][lrow] = xa1.y;
        Xs[lk + 6][lrow] = xa1.z; Xs[lk + 7][lrow] = xa1.w;
        Ws[lk + 0][lrow] = wa0.x; Ws[lk + 1][lrow] = wa0.y;
        Ws[lk + 2][lrow] = wa0.z; Ws[lk + 3][lrow] = wa0.w;
        Ws[lk + 4][lrow] = wa1.x; Ws[lk + 5][lrow] = wa1.y;
        Ws[lk + 6][lrow] = wa1.z; Ws[lk + 7][lrow] = wa1.w;
        __syncthreads();

        if (kb + 16 < HID) {
            ld8_guard(xbase + kb + 16, xok, xa0, xa1);
            wa0 = *(const float4*)(wbase + kb + 16);
            wa1 = *(const float4*)(wbase + kb + 16 + 4);
        }

#pragma unroll
        for (int k = 0; k < 16; k++) {
            float4 a0 = *(const float4*)&Xs[k][tm];
            float4 a1 = *(const float4*)&Xs[k][tm + 4];
            ulonglong2 b01 = *(const ulonglong2*)&Ws[k][tn];
            ulonglong2 b23 = *(const ulonglong2*)&Ws[k][tn + 4];
            ull A[8];
            A[0] = pack2(a0.x); A[1] = pack2(a0.y);
            A[2] = pack2(a0.z); A[3] = pack2(a0.w);
            A[4] = pack2(a1.x); A[5] = pack2(a1.y);
            A[6] = pack2(a1.z); A[7] = pack2(a1.w);
#pragma unroll
            for (int i = 0; i < 8; i++) {
                acc[i][0] = fma2(A[i], b01.x, acc[i][0]);
                acc[i][1] = fma2(A[i], b01.y, acc[i][1]);
                acc[i][2] = fma2(A[i], b23.x, acc[i][2]);
                acc[i][3] = fma2(A[i], b23.y, acc[i][3]);
            }
        }
        __syncthreads();
    }

    float bv[8];
    if (bias) {
#pragma unroll
        for (int j = 0; j < 8; j++) bv[j] = bias[col0 + tn + j];
    } else {
#pragma unroll
        for (int j = 0; j < 8; j++) bv[j] = 0.f;
    }

#pragma unroll
    for (int i = 0; i < 8; i++) {
        int grow = row0 + tm + i;
        if (grow < total) {
            float2 f0 = unpack2(acc[i][0]);
            float2 f1 = unpack2(acc[i][1]);
            float2 f2 = unpack2(acc[i][2]);
            float2 f3 = unpack2(acc[i][3]);
            float* p = Out + (size_t)grow * HID + col0 + tn;
            *(float4*)p = make_float4(f0.x + bv[0], f0.y + bv[1],
                                      f1.x + bv[2], f1.y + bv[3]);
            *(float4*)(p + 4) = make_float4(f2.x + bv[4], f2.y + bv[5],
                                            f3.x + bv[6], f3.y + bv[7]);
        }
    }
}

__global__ void __launch_bounds__(256, 2)
qkv_kernel(const float* __restrict__ msg,
           const float* __restrict__ Wq,
           const float* __restrict__ Wk,
           const float* __restrict__ Wv,
           int total) {
    const int y = blockIdx.y;            // 0..5
    const int mat = y >> 1;
    const int col0 = (y & 1) * 128;
    const float* W = (mat == 0) ? Wq : (mat == 1 ? Wk : Wv);
    float* Out = (mat == 0) ? g_Q : (mat == 1 ? g_K : g_V);
    gemm128(msg, W, Out, nullptr, total, blockIdx.x * 128, col0);
}

__global__ void __launch_bounds__(256, 2)
proj_kernel(const float* __restrict__ Wo,
            const float* __restrict__ bo,
            int total) {
    gemm128(g_O, Wo, g_Y, bo, total, blockIdx.x * 128, blockIdx.y * 128);
}

// ---------------------------------------------------------------------------
// Attention: per-(mol, head) CTA, thread j = query j, online softmax, FFMA2.
// smem = K/V tiles only (64 KB) -> 3 CTAs/SM.
// ---------------------------------------------------------------------------
#define ATTN_SMEM (2 * 128 * DH * 4)

__global__ void __launch_bounds__(128)
attn_kernel(const int* __restrict__ b_starts,
            const int* __restrict__ b_sizes) {
    extern __shared__ float sm[];
    float* kS = sm;                      // [128][64]
    float* vS = sm + 128 * DH;           // [128][64]

    const int m = blockIdx.x;
    const int h = blockIdx.y;
    const int S = b_sizes[m];
    const int start = b_starts[m];
    const int tid = threadIdx.x;

    for (int idx = tid; idx < S * 16; idx += 128) {
        int i = idx >> 4, d = (idx & 15) * 4;
        size_t g = (size_t)(start + i) * HID + h * DH + d;
        *(float4*)(kS + i * DH + d) = *(const float4*)(g_K + g);
        *(float4*)(vS + i * DH + d) = *(const float4*)(g_V + g);
    }
    __syncthreads();

    if (tid < S) {
        const float* qp = g_Q + (size_t)(start + tid) * HID + h * DH;
        ull q2[32];
#pragma unroll
        for (int j = 0; j < 16; j++) {
            ulonglong2 t = *(const ulonglong2*)(qp + 4 * j);
            q2[2 * j] = t.x;
            q2[2 * j + 1] = t.y;
        }

        float mx = -3.0e38f, l = 0.f;
        ull o2[32];
#pragma unroll
        for (int d = 0; d < 32; d++) o2[d] = 0ull;

        for (int i = 0; i < S; i++) {
            const ull* kp = (const ull*)(kS + i * DH);
            ull s2 = 0ull;
#pragma unroll
            for (int d = 0; d < 32; d++) s2 = fma2(q2[d], kp[d], s2);
            float2 sf = unpack2(s2);
            float s = (sf.x + sf.y) * 0.125f;

            if (s > mx) {
                float c = __expf(mx - s);
                l *= c;
                ull c2 = pack2(c);
#pragma unroll
                for (int d = 0; d < 32; d++) o2[d] = mul2(o2[d], c2);
                mx = s;
            }
            float e = __expf(s - mx);
            l += e;
            ull e2 = pack2(e);
            const ull* vp = (const ull*)(vS + i * DH);
#pragma unroll
            for (int d = 0; d < 32; d++) o2[d] = fma2(e2, vp[d], o2[d]);
        }

        float inv = 1.0f / l;
        float* op = g_O + (size_t)(start + tid) * HID + h * DH;
#pragma unroll
        for (int d = 0; d < 32; d += 2) {
            float2 f0 = unpack2(o2[d]);
            float2 f1 = unpack2(o2[d + 1]);
            float4 v = make_float4(fmaxf(f0.x * inv, 0.f),
                                   fmaxf(f0.y * inv, 0.f),
                                   fmaxf(f1.x * inv, 0.f),
                                   fmaxf(f1.y * inv, 0.f));
            *(float4*)(op + 2 * d) = v;
        }
    }
}

// ---------------------------------------------------------------------------
// LayerNorm: one warp per row; row 0 forced to zero.
// ---------------------------------------------------------------------------
__global__ void __launch_bounds__(256)
ln_kernel(const float* __restrict__ gamma,
          const float* __restrict__ beta,
          float* __restrict__ out,
          int total) {
    const int row = blockIdx.x * 8 + (threadIdx.x >> 5);
    if (row >= total) return;
    const int lane = threadIdx.x & 31;

    const float* y = g_Y + (size_t)row * HID;
    float4 v0 = *(const float4*)(y + lane * 4);
    float4 v1 = *(const float4*)(y + 128 + lane * 4);

    float s = v0.x + v0.y + v0.z + v0.w + v1.x + v1.y + v1.z + v1.w;
#pragma unroll
    for (int off = 16; off > 0; off >>= 1) s += __shfl_xor_sync(0xffffffffu, s, off);
    float mu = s * (1.f / 256.f);

    float q = 0.f;
    {
        float d;
        d = v0.x - mu; q += d * d; d = v0.y - mu; q += d * d;
        d = v0.z - mu; q += d * d; d = v0.w - mu; q += d * d;
        d = v1.x - mu; q += d * d; d = v1.y - mu; q += d * d;
        d = v1.z - mu; q += d * d; d = v1.w - mu; q += d * d;
    }
#pragma unroll
    for (int off = 16; off > 0; off >>= 1) q += __shfl_xor_sync(0xffffffffu, q, off);
    float rsig = rsqrtf(q * (1.f / 256.f) + 1e-5f);

    float* op = out + (size_t)row * HID;
    if (row == 0) {
        *(float4*)(op + lane * 4) = make_float4(0.f, 0.f, 0.f, 0.f);
        *(float4*)(op + 128 + lane * 4) = make_float4(0.f, 0.f, 0.f, 0.f);
    } else {
        float4 g0 = *(const float4*)(gamma + lane * 4);
        float4 g1 = *(const float4*)(gamma + 128 + lane * 4);
        float4 b0 = *(const float4*)(beta + lane * 4);
        float4 b1 = *(const float4*)(beta + 128 + lane * 4);
        float4 r0 = make_float4((v0.x - mu) * rsig * g0.x + b0.x,
                                (v0.y - mu) * rsig * g0.y + b0.y,
                                (v0.z - mu) * rsig * g0.z + b0.z,
                                (v0.w - mu) * rsig * g0.w + b0.w);
        float4 r1 = make_float4((v1.x - mu) * rsig * g1.x + b1.x,
                                (v1.y - mu) * rsig * g1.y + b1.y,
                                (v1.z - mu) * rsig * g1.z + b1.z,
                                (v1.w - mu) * rsig * g1.w + b1.w);
        *(float4*)(op + lane * 4) = r0;
        *(float4*)(op + 128 + lane * 4) = r1;
    }
}

// ---------------------------------------------------------------------------
extern "C" void kernel_launch(void* const* d_in, const int* in_sizes, int n_in,
                              void* d_out, int out_size) {
    const float* msg      = (const float*)d_in[0];
    const float* Wq       = (const float*)d_in[1];
    const float* Wk       = (const float*)d_in[2];
    const float* Wv       = (const float*)d_in[3];
    const float* Wo       = (const float*)d_in[4];
    const float* bo       = (const float*)d_in[5];
    const float* gamma    = (const float*)d_in[6];
    const float* beta     = (const float*)d_in[7];
    const int*   b_starts = (const int*)d_in[8];
    const int*   b_sizes  = (const int*)d_in[9];
    float* out = (float*)d_out;

    const int total = in_sizes[0] / HID;

    cudaFuncSetAttribute(attn_kernel,
                         cudaFuncAttributeMaxDynamicSharedMemorySize, ATTN_SMEM);

    dim3 ga((total + 127) / 128, 6);
    qkv_kernel<<<ga, 256>>>(msg, Wq, Wk, Wv, total);

    dim3 gb(N_MOLS, NH);
    attn_kernel<<<gb, 128, ATTN_SMEM>>>(b_starts, b_sizes);

    dim3 gc((total + 127) / 128, 2);
    proj_kernel<<<gc, 256>>>(Wo, bo, total);

    ln_kernel<<<(total + 7) / 8, 256>>>(gamma, beta, out, total);
}

// round 7
// speedup vs baseline: 3.3205x; 1.6667x over previous
#include <cuda_runtime.h>
#include <cuda_fp16.h>
#include <cstdint>

#define HID 256
#define NH 4
#define DH 64
#define N_MOLS 2048
#define MAX_LEN 128
#define MAX_TOTAL (1 + N_MOLS * MAX_LEN)

typedef unsigned long long ull;

// Scratch (device globals: allocation-free rule). fp16 for Q/K/V/O, fp32 for Y.
__device__ unsigned short g_Qh_u[(size_t)MAX_TOTAL * HID];
__device__ unsigned short g_Kh_u[(size_t)MAX_TOTAL * HID];
__device__ unsigned short g_Vh_u[(size_t)MAX_TOTAL * HID];
__device__ unsigned short g_Oh_u[(size_t)MAX_TOTAL * HID];
__device__ float g_Y[(size_t)MAX_TOTAL * HID];

#define g_Qh ((__half*)g_Qh_u)
#define g_Kh ((__half*)g_Kh_u)
#define g_Vh ((__half*)g_Vh_u)
#define g_Oh ((__half*)g_Oh_u)

// ============================ helpers =======================================
__device__ __forceinline__ uint32_t smem_u32(const void* p) {
    uint32_t a;
    asm("{ .reg .u64 t; cvta.to.shared.u64 t, %1; cvt.u32.u64 %0, t; }"
        : "=r"(a) : "l"(p));
    return a;
}
__device__ __forceinline__ uint32_t h2u(__half2 h) {
    return *reinterpret_cast<uint32_t*>(&h);
}

// ---- packed f32x2 helpers (FFMA2) ----
__device__ __forceinline__ ull pack2(float x) {
    ull d; unsigned u = __float_as_uint(x);
    asm("mov.b64 %0, {%1, %1};" : "=l"(d) : "r"(u));
    return d;
}
__device__ __forceinline__ ull pack2f(float x, float y) {
    ull d;
    asm("mov.b64 %0, {%1, %2};" : "=l"(d)
        : "r"(__float_as_uint(x)), "r"(__float_as_uint(y)));
    return d;
}
__device__ __forceinline__ float2 unpack2(ull v) {
    unsigned lo, hi;
    asm("mov.b64 {%0, %1}, %2;" : "=r"(lo), "=r"(hi) : "l"(v));
    return make_float2(__uint_as_float(lo), __uint_as_float(hi));
}
__device__ __forceinline__ ull fma2(ull a, ull b, ull c) {
    ull d;
    asm("fma.rn.f32x2 %0, %1, %2, %3;" : "=l"(d) : "l"(a), "l"(b), "l"(c));
    return d;
}
__device__ __forceinline__ ull mul2(ull a, ull b) {
    ull d;
    asm("mul.rn.f32x2 %0, %1, %2;" : "=l"(d) : "l"(a), "l"(b));
    return d;
}
__device__ __forceinline__ ull add2(ull a, ull b) {
    ull d;
    asm("add.rn.f32x2 %0, %1, %2;" : "=l"(d) : "l"(a), "l"(b));
    return d;
}

// ---- mma.sync / ldmatrix (baseline features, assemble on plain sm_103) ----
#define LDMX4(r, addr) \
    asm volatile("ldmatrix.sync.aligned.m8n8.x4.shared.b16 {%0,%1,%2,%3}, [%4];" \
                 : "=r"((r)[0]), "=r"((r)[1]), "=r"((r)[2]), "=r"((r)[3]) \
                 : "r"(addr))

#define MMA16816(d, a, b) \
    asm volatile("mma.sync.aligned.m16n8k16.row.col.f32.f16.f16.f32 " \
                 "{%0,%1,%2,%3}, {%4,%5,%6,%7}, {%8,%9}, {%0,%1,%2,%3};" \
                 : "+f"((d)[0]), "+f"((d)[1]), "+f"((d)[2]), "+f"((d)[3]) \
                 : "r"((a)[0]), "r"((a)[1]), "r"((a)[2]), "r"((a)[3]), \
                   "r"((b)[0]), "r"((b)[1]))

// ======================= fp16 HMMA GEMM (128x128 tile) ======================
// Out[r][c] = sum_k A[r][k] * W[c][k] (+bias).
// 256 threads, 8 warps in 2(m)x4(n); warp tile 64x32; BK=128 halves, 2 chunks.
#define LDA 136                       // halves per smem row (128 + 8 pad)
#define GEMM_SMEM (2 * 128 * LDA * 2) // A + B, bytes = 69632

template <bool A_HALF, bool OUT_HALF>
__device__ __forceinline__ void gemm_body(const float* __restrict__ Af,
                                          const __half* __restrict__ Ah,
                                          const float* __restrict__ W,
                                          float* __restrict__ OutF,
                                          __half* __restrict__ OutH,
                                          const float* __restrict__ bias,
                                          int total, int row0, int c0) {
    extern __shared__ __half sh[];
    __half* sA = sh;
    __half* sB = sh + 128 * LDA;

    const int tid = threadIdx.x;
    const int lane = tid & 31;
    const int wid = tid >> 5;

    float acc[4][4][4];
#pragma unroll
    for (int f = 0; f < 4; f++)
#pragma unroll
        for (int j = 0; j < 4; j++)
#pragma unroll
            for (int e = 0; e < 4; e++) acc[f][j][e] = 0.f;

    const int srow = tid >> 1;           // 0..127
    const int sseg = tid & 1;            // 64-half segment
    const bool aok = (row0 + srow) < total;

    const uint32_t aBase = smem_u32(sA);
    const uint32_t bBase = smem_u32(sB);
    const int warp_m = (wid >> 2) * 64;
    const int warp_n = (wid & 3) * 32;
    const uint32_t aLaneOff = (uint32_t)(((lane & 15) * LDA + (lane >> 4) * 8) * 2);
    const uint32_t bLaneRow = (uint32_t)(((lane >> 4) << 3) + (lane & 7));
    const uint32_t bLaneCol = (uint32_t)(((lane >> 3) & 1) * 8);

#pragma unroll
    for (int kc = 0; kc < 2; kc++) {
        const int k0 = kc * 128;
        if (kc) __syncthreads();

        // ---- stage A chunk (64 halves = 8 x uint4, contiguous) ----
        {
            __half* dst = sA + srow * LDA + sseg * 64;
            if (A_HALF) {
                const __half* p = Ah + (size_t)(row0 + srow) * HID + k0 + sseg * 64;
#pragma unroll
                for (int j = 0; j < 8; j++) {
                    uint4 v = aok ? *(const uint4*)(p + j * 8)
                                  : make_uint4(0, 0, 0, 0);
                    *(uint4*)(dst + j * 8) = v;
                }
            } else {
                const float* p = Af + (size_t)(row0 + srow) * HID + k0 + sseg * 64;
#pragma unroll
                for (int j = 0; j < 8; j++) {
                    float4 v0, v1;
                    if (aok) {
                        v0 = *(const float4*)(p + j * 8);
                        v1 = *(const float4*)(p + j * 8 + 4);
                    } else {
                        v0 = make_float4(0.f, 0.f, 0.f, 0.f);
                        v1 = v0;
                    }
                    uint4 w;
                    w.x = h2u(__floats2half2_rn(v0.x, v0.y));
                    w.y = h2u(__floats2half2_rn(v0.z, v0.w));
                    w.z = h2u(__floats2half2_rn(v1.x, v1.y));
                    w.w = h2u(__floats2half2_rn(v1.z, v1.w));
                    *(uint4*)(dst + j * 8) = w;
                }
            }
        }
        // ---- stage B chunk (W rows c0+srow) ----
        {
            const float* p = W + (size_t)(c0 + srow) * HID + k0 + sseg * 64;
            __half* dst = sB + srow * LDA + sseg * 64;
#pragma unroll
            for (int j = 0; j < 8; j++) {
                float4 v0 = *(const float4*)(p + j * 8);
                float4 v1 = *(const float4*)(p + j * 8 + 4);
                uint4 w;
                w.x = h2u(__floats2half2_rn(v0.x, v0.y));
                w.y = h2u(__floats2half2_rn(v0.z, v0.w));
                w.z = h2u(__floats2half2_rn(v1.x, v1.y));
                w.w = h2u(__floats2half2_rn(v1.z, v1.w));
                *(uint4*)(dst + j * 8) = w;
            }
        }
        __syncthreads();

        // ---- compute chunk: 8 k-steps of 16 ----
#pragma unroll
        for (int ks = 0; ks < 8; ks++) {
            uint32_t a[4][4];
            uint32_t b[4][2];
#pragma unroll
            for (int f = 0; f < 4; f++) {
                uint32_t addr = aBase +
                    (uint32_t)(((warp_m + f * 16) * LDA + ks * 16) * 2) + aLaneOff;
                LDMX4(a[f], addr);
            }
#pragma unroll
            for (int g = 0; g < 2; g++) {
                uint32_t addr = bBase +
                    (uint32_t)(((warp_n + g * 16 + bLaneRow) * LDA +
                                ks * 16 + bLaneCol) * 2);
                uint32_t r[4];
                LDMX4(r, addr);
                b[2 * g][0] = r[0]; b[2 * g][1] = r[1];
                b[2 * g + 1][0] = r[2]; b[2 * g + 1][1] = r[3];
            }
#pragma unroll
            for (int f = 0; f < 4; f++)
#pragma unroll
                for (int j = 0; j < 4; j++)
                    MMA16816(acc[f][j], a[f], b[j]);
        }
    }

    // ---- epilogue ----
#pragma unroll
    for (int f = 0; f < 4; f++) {
        const int row_lo = row0 + warp_m + f * 16 + (lane >> 2);
        const int row_hi = row_lo + 8;
        const bool ok_lo = row_lo < total;
        const bool ok_hi = row_hi < total;
#pragma unroll
        for (int j = 0; j < 4; j++) {
            const int col = c0 + warp_n + j * 8 + (lane & 3) * 2;
            if (OUT_HALF) {
                if (ok_lo)
                    *(__half2*)(OutH + (size_t)row_lo * HID + col) =
                        __floats2half2_rn(acc[f][j][0], acc[f][j][1]);
                if (ok_hi)
                    *(__half2*)(OutH + (size_t)row_hi * HID + col) =
                        __floats2half2_rn(acc[f][j][2], acc[f][j][3]);
            } else {
                float2 bb = *(const float2*)(bias + col);
                if (ok_lo)
                    *(float2*)(OutF + (size_t)row_lo * HID + col) =
                        make_float2(acc[f][j][0] + bb.x, acc[f][j][1] + bb.y);
                if (ok_hi)
                    *(float2*)(OutF + (size_t)row_hi * HID + col) =
                        make_float2(acc[f][j][2] + bb.x, acc[f][j][3] + bb.y);
            }
        }
    }
}

__global__ void __launch_bounds__(256, 2)
qkv_mma_kernel(const float* __restrict__ msg,
               const float* __restrict__ Wq,
               const float* __restrict__ Wk,
               const float* __restrict__ Wv,
               int total) {
    const int bx = blockIdx.x;            // 0..5, fastest -> X-tile L2 reuse
    const int mat = bx >> 1;
    const int c0 = (bx & 1) * 128;
    const float* W = (mat == 0) ? Wq : (mat == 1 ? Wk : Wv);
    __half* Out = (mat == 0) ? g_Qh : (mat == 1 ? g_Kh : g_Vh);
    gemm_body<false, true>(msg, nullptr, W, nullptr, Out, nullptr,
                           total, blockIdx.y * 128, c0);
}

__global__ void __launch_bounds__(256, 2)
proj_mma_kernel(const float* __restrict__ Wo,
                const float* __restrict__ bo,
                int total) {
    gemm_body<true, false>(nullptr, g_Oh, Wo, g_Y, nullptr, bo,
                           total, blockIdx.y * 128, blockIdx.x * 128);
}

// ======================= Attention (fp32 math, online softmax) ==============
#define ATTN_SMEM (2 * 128 * DH * 4)

__global__ void __launch_bounds__(128)
attn_kernel(const int* __restrict__ b_starts,
            const int* __restrict__ b_sizes) {
    extern __shared__ float sm[];
    float* kS = sm;                      // [128][64]
    float* vS = sm + 128 * DH;           // [128][64]

    const int m = blockIdx.x;
    const int h = blockIdx.y;
    const int S = b_sizes[m];
    const int start = b_starts[m];
    const int tid = threadIdx.x;

    // stage K/V (fp16 -> fp32 smem)
    for (int idx = tid; idx < S * 8; idx += 128) {
        int i = idx >> 3, c = (idx & 7) * 8;
        size_t g = (size_t)(start + i) * HID + h * DH + c;
        uint4 kv = *(const uint4*)(g_Kh + g);
        uint4 vv = *(const uint4*)(g_Vh + g);
        const __half2* hk = (const __half2*)&kv;
        const __half2* hv = (const __half2*)&vv;
        float2 k0 = __half22float2(hk[0]), k1 = __half22float2(hk[1]);
        float2 k2 = __half22float2(hk[2]), k3 = __half22float2(hk[3]);
        float2 v0 = __half22float2(hv[0]), v1 = __half22float2(hv[1]);
        float2 v2 = __half22float2(hv[2]), v3 = __half22float2(hv[3]);
        *(float4*)(kS + i * DH + c)     = make_float4(k0.x, k0.y, k1.x, k1.y);
        *(float4*)(kS + i * DH + c + 4) = make_float4(k2.x, k2.y, k3.x, k3.y);
        *(float4*)(vS + i * DH + c)     = make_float4(v0.x, v0.y, v1.x, v1.y);
        *(float4*)(vS + i * DH + c + 4) = make_float4(v2.x, v2.y, v3.x, v3.y);
    }
    __syncthreads();

    if (tid < S) {
        const __half* qp = g_Qh + (size_t)(start + tid) * HID + h * DH;
        ull q2[32];
#pragma unroll
        for (int j = 0; j < 8; j++) {
            uint4 v = ((const uint4*)qp)[j];
            const __half2* hh = (const __half2*)&v;
#pragma unroll
            for (int w = 0; w < 4; w++) {
                float2 f = __half22float2(hh[w]);
                q2[j * 4 + w] = pack2f(f.x, f.y);
            }
        }

        float mx = -3.0e38f, l = 0.f;
        ull o2[32];
#pragma unroll
        for (int d = 0; d < 32; d++) o2[d] = 0ull;

        for (int i = 0; i < S; i++) {
            const ulonglong2* kp = (const ulonglong2*)(kS + i * DH);
            ull a0 = 0ull, a1 = 0ull, a2 = 0ull, a3 = 0ull;
#pragma unroll
            for (int t = 0; t < 16; t += 2) {
                ulonglong2 k0 = kp[t];
                ulonglong2 k1 = kp[t + 1];
                a0 = fma2(q2[2 * t + 0], k0.x, a0);
                a1 = fma2(q2[2 * t + 1], k0.y, a1);
                a2 = fma2(q2[2 * t + 2], k1.x, a2);
                a3 = fma2(q2[2 * t + 3], k1.y, a3);
            }
            float2 sf = unpack2(add2(add2(a0, a1), add2(a2, a3)));
            float sv = (sf.x + sf.y) * 0.125f;

            if (sv > mx) {
                float c = __expf(mx - sv);
                l *= c;
                ull c2 = pack2(c);
#pragma unroll
                for (int d = 0; d < 32; d++) o2[d] = mul2(o2[d], c2);
                mx = sv;
            }
            float e = __expf(sv - mx);
            l += e;
            ull e2 = pack2(e);
            const ulonglong2* vp = (const ulonglong2*)(vS + i * DH);
#pragma unroll
            for (int t = 0; t < 16; t++) {
                ulonglong2 vv = vp[t];
                o2[2 * t + 0] = fma2(e2, vv.x, o2[2 * t + 0]);
                o2[2 * t + 1] = fma2(e2, vv.y, o2[2 * t + 1]);
            }
        }

        float inv = 1.0f / l;
        __half* op = g_Oh + (size_t)(start + tid) * HID + h * DH;
#pragma unroll
        for (int d = 0; d < 32; d += 4) {
            uint4 w;
            float2 f0 = unpack2(o2[d + 0]);
            float2 f1 = unpack2(o2[d + 1]);
            float2 f2 = unpack2(o2[d + 2]);
            float2 f3 = unpack2(o2[d + 3]);
            w.x = h2u(__floats2half2_rn(fmaxf(f0.x * inv, 0.f), fmaxf(f0.y * inv, 0.f)));
            w.y = h2u(__floats2half2_rn(fmaxf(f1.x * inv, 0.f), fmaxf(f1.y * inv, 0.f)));
            w.z = h2u(__floats2half2_rn(fmaxf(f2.x * inv, 0.f), fmaxf(f2.y * inv, 0.f)));
            w.w = h2u(__floats2half2_rn(fmaxf(f3.x * inv, 0.f), fmaxf(f3.y * inv, 0.f)));
            *(uint4*)(op + 2 * d) = w;
        }
    }
}

// ======================= LayerNorm ==========================================
__global__ void __launch_bounds__(256)
ln_kernel(const float* __restrict__ gamma,
          const float* __restrict__ beta,
          float* __restrict__ out,
          int total) {
    const int row = blockIdx.x * 8 + (threadIdx.x >> 5);
    if (row >= total) return;
    const int lane = threadIdx.x & 31;

    const float* y = g_Y + (size_t)row * HID;
    float4 v0 = *(const float4*)(y + lane * 4);
    float4 v1 = *(const float4*)(y + 128 + lane * 4);

    float s = v0.x + v0.y + v0.z + v0.w + v1.x + v1.y + v1.z + v1.w;
#pragma unroll
    for (int off = 16; off > 0; off >>= 1) s += __shfl_xor_sync(0xffffffffu, s, off);
    float mu = s * (1.f / 256.f);

    float q = 0.f;
    {
        float d;
        d = v0.x - mu; q += d * d; d = v0.y - mu; q += d * d;
        d = v0.z - mu; q += d * d; d = v0.w - mu; q += d * d;
        d = v1.x - mu; q += d * d; d = v1.y - mu; q += d * d;
        d = v1.z - mu; q += d * d; d = v1.w - mu; q += d * d;
    }
#pragma unroll
    for (int off = 16; off > 0; off >>= 1) q += __shfl_xor_sync(0xffffffffu, q, off);
    float rsig = rsqrtf(q * (1.f / 256.f) + 1e-5f);

    float* op = out + (size_t)row * HID;
    if (row == 0) {
        *(float4*)(op + lane * 4) = make_float4(0.f, 0.f, 0.f, 0.f);
        *(float4*)(op + 128 + lane * 4) = make_float4(0.f, 0.f, 0.f, 0.f);
    } else {
        float4 g0 = *(const float4*)(gamma + lane * 4);
        float4 g1 = *(const float4*)(gamma + 128 + lane * 4);
        float4 b0 = *(const float4*)(beta + lane * 4);
        float4 b1 = *(const float4*)(beta + 128 + lane * 4);
        float4 r0 = make_float4((v0.x - mu) * rsig * g0.x + b0.x,
                                (v0.y - mu) * rsig * g0.y + b0.y,
                                (v0.z - mu) * rsig * g0.z + b0.z,
                                (v0.w - mu) * rsig * g0.w + b0.w);
        float4 r1 = make_float4((v1.x - mu) * rsig * g1.x + b1.x,
                                (v1.y - mu) * rsig * g1.y + b1.y,
                                (v1.z - mu) * rsig * g1.z + b1.z,
                                (v1.w - mu) * rsig * g1.w + b1.w);
        *(float4*)(op + lane * 4) = r0;
        *(float4*)(op + 128 + lane * 4) = r1;
    }
}

// ---------------------------------------------------------------------------
extern "C" void kernel_launch(void* const* d_in, const int* in_sizes, int n_in,
                              void* d_out, int out_size) {
    const float* msg      = (const float*)d_in[0];
    const float* Wq       = (const float*)d_in[1];
    const float* Wk       = (const float*)d_in[2];
    const float* Wv       = (const float*)d_in[3];
    const float* Wo       = (const float*)d_in[4];
    const float* bo       = (const float*)d_in[5];
    const float* gamma    = (const float*)d_in[6];
    const float* beta     = (const float*)d_in[7];
    const int*   b_starts = (const int*)d_in[8];
    const int*   b_sizes  = (const int*)d_in[9];
    float* out = (float*)d_out;

    const int total = in_sizes[0] / HID;
    const int tiles = (total + 127) / 128;

    cudaFuncSetAttribute(qkv_mma_kernel,
                         cudaFuncAttributeMaxDynamicSharedMemorySize, GEMM_SMEM);
    cudaFuncSetAttribute(proj_mma_kernel,
                         cudaFuncAttributeMaxDynamicSharedMemorySize, GEMM_SMEM);
    cudaFuncSetAttribute(attn_kernel,
                         cudaFuncAttributeMaxDynamicSharedMemorySize, ATTN_SMEM);

    dim3 ga(6, tiles);
    qkv_mma_kernel<<<ga, 256, GEMM_SMEM>>>(msg, Wq, Wk, Wv, total);

    dim3 gb(N_MOLS, NH);
    attn_kernel<<<gb, 128, ATTN_SMEM>>>(b_starts, b_sizes);

    dim3 gc(2, tiles);
    proj_mma_kernel<<<gc, 256, GEMM_SMEM>>>(Wo, bo, total);

    ln_kernel<<<(total + 7) / 8, 256>>>(gamma, beta, out, total);
}

// round 8
// speedup vs baseline: 5.2888x; 1.5928x over previous
#include <cuda_runtime.h>
#include <cuda_fp16.h>
#include <cstdint>

#define HID 256
#define NH 4
#define DH 64
#define N_MOLS 2048
#define MAX_LEN 128
#define MAX_TOTAL (1 + N_MOLS * MAX_LEN)

// Scratch (device globals: allocation-free rule). fp16 for Q/K/V/O, fp32 for Y.
__device__ unsigned short g_Qh_u[(size_t)MAX_TOTAL * HID];
__device__ unsigned short g_Kh_u[(size_t)MAX_TOTAL * HID];
__device__ unsigned short g_Vh_u[(size_t)MAX_TOTAL * HID];
__device__ unsigned short g_Oh_u[(size_t)MAX_TOTAL * HID];
__device__ float g_Y[(size_t)MAX_TOTAL * HID];

#define g_Qh ((__half*)g_Qh_u)
#define g_Kh ((__half*)g_Kh_u)
#define g_Vh ((__half*)g_Vh_u)
#define g_Oh ((__half*)g_Oh_u)

// ============================ helpers =======================================
__device__ __forceinline__ uint32_t smem_u32(const void* p) {
    uint32_t a;
    asm("{ .reg .u64 t; cvta.to.shared.u64 t, %1; cvt.u32.u64 %0, t; }"
        : "=r"(a) : "l"(p));
    return a;
}
__device__ __forceinline__ uint32_t h2u(__half2 h) {
    return *reinterpret_cast<uint32_t*>(&h);
}

// ---- mma.sync / ldmatrix (baseline features, assemble on plain sm_103) ----
#define LDMX4(r, addr) \
    asm volatile("ldmatrix.sync.aligned.m8n8.x4.shared.b16 {%0,%1,%2,%3}, [%4];" \
                 : "=r"((r)[0]), "=r"((r)[1]), "=r"((r)[2]), "=r"((r)[3]) \
                 : "r"(addr))

#define MMA16816(d, a, b) \
    asm volatile("mma.sync.aligned.m16n8k16.row.col.f32.f16.f16.f32 " \
                 "{%0,%1,%2,%3}, {%4,%5,%6,%7}, {%8,%9}, {%0,%1,%2,%3};" \
                 : "+f"((d)[0]), "+f"((d)[1]), "+f"((d)[2]), "+f"((d)[3]) \
                 : "r"((a)[0]), "r"((a)[1]), "r"((a)[2]), "r"((a)[3]), \
                   "r"((b)[0]), "r"((b)[1]))

// ======================= fp16 HMMA GEMM (128x128 tile) ======================
#define LDA 136                       // halves per smem row (128 + 8 pad)
#define GEMM_SMEM (2 * 128 * LDA * 2) // A + B, bytes = 69632

template <bool A_HALF, bool OUT_HALF>
__device__ __forceinline__ void gemm_body(const float* __restrict__ Af,
                                          const __half* __restrict__ Ah,
                                          const float* __restrict__ W,
                                          float* __restrict__ OutF,
                                          __half* __restrict__ OutH,
                                          const float* __restrict__ bias,
                                          int total, int row0, int c0) {
    extern __shared__ __half sh[];
    __half* sA = sh;
    __half* sB = sh + 128 * LDA;

    const int tid = threadIdx.x;
    const int lane = tid & 31;
    const int wid = tid >> 5;

    float acc[4][4][4];
#pragma unroll
    for (int f = 0; f < 4; f++)
#pragma unroll
        for (int j = 0; j < 4; j++)
#pragma unroll
            for (int e = 0; e < 4; e++) acc[f][j][e] = 0.f;

    const int srow = tid >> 1;           // 0..127
    const int sseg = tid & 1;            // 64-half segment
    const bool aok = (row0 + srow) < total;

    const uint32_t aBase = smem_u32(sA);
    const uint32_t bBase = smem_u32(sB);
    const int warp_m = (wid >> 2) * 64;
    const int warp_n = (wid & 3) * 32;
    const uint32_t aLaneOff = (uint32_t)(((lane & 15) * LDA + (lane >> 4) * 8) * 2);
    const uint32_t bLaneRow = (uint32_t)(((lane >> 4) << 3) + (lane & 7));
    const uint32_t bLaneCol = (uint32_t)(((lane >> 3) & 1) * 8);

#pragma unroll
    for (int kc = 0; kc < 2; kc++) {
        const int k0 = kc * 128;
        if (kc) __syncthreads();

        // ---- stage A chunk (64 halves, contiguous) ----
        {
            __half* dst = sA + srow * LDA + sseg * 64;
            if (A_HALF) {
                const __half* p = Ah + (size_t)(row0 + srow) * HID + k0 + sseg * 64;
#pragma unroll
                for (int j = 0; j < 8; j++) {
                    uint4 v = aok ? *(const uint4*)(p + j * 8)
                                  : make_uint4(0, 0, 0, 0);
                    *(uint4*)(dst + j * 8) = v;
                }
            } else {
                const float* p = Af + (size_t)(row0 + srow) * HID + k0 + sseg * 64;
#pragma unroll
                for (int j = 0; j < 8; j++) {
                    float4 v0, v1;
                    if (aok) {
                        v0 = *(const float4*)(p + j * 8);
                        v1 = *(const float4*)(p + j * 8 + 4);
                    } else {
                        v0 = make_float4(0.f, 0.f, 0.f, 0.f);
                        v1 = v0;
                    }
                    uint4 w;
                    w.x = h2u(__floats2half2_rn(v0.x, v0.y));
                    w.y = h2u(__floats2half2_rn(v0.z, v0.w));
                    w.z = h2u(__floats2half2_rn(v1.x, v1.y));
                    w.w = h2u(__floats2half2_rn(v1.z, v1.w));
                    *(uint4*)(dst + j * 8) = w;
                }
            }
        }
        // ---- stage B chunk (W rows c0+srow) ----
        {
            const float* p = W + (size_t)(c0 + srow) * HID + k0 + sseg * 64;
            __half* dst = sB + srow * LDA + sseg * 64;
#pragma unroll
            for (int j = 0; j < 8; j++) {
                float4 v0 = *(const float4*)(p + j * 8);
                float4 v1 = *(const float4*)(p + j * 8 + 4);
                uint4 w;
                w.x = h2u(__floats2half2_rn(v0.x, v0.y));
                w.y = h2u(__floats2half2_rn(v0.z, v0.w));
                w.z = h2u(__floats2half2_rn(v1.x, v1.y));
                w.w = h2u(__floats2half2_rn(v1.z, v1.w));
                *(uint4*)(dst + j * 8) = w;
            }
        }
        __syncthreads();

        // ---- compute chunk: 8 k-steps of 16 ----
#pragma unroll
        for (int ks = 0; ks < 8; ks++) {
            uint32_t a[4][4];
            uint32_t b[4][2];
#pragma unroll
            for (int f = 0; f < 4; f++) {
                uint32_t addr = aBase +
                    (uint32_t)(((warp_m + f * 16) * LDA + ks * 16) * 2) + aLaneOff;
                LDMX4(a[f], addr);
            }
#pragma unroll
            for (int g = 0; g < 2; g++) {
                uint32_t addr = bBase +
                    (uint32_t)(((warp_n + g * 16 + bLaneRow) * LDA +
                                ks * 16 + bLaneCol) * 2);
                uint32_t r[4];
                LDMX4(r, addr);
                b[2 * g][0] = r[0]; b[2 * g][1] = r[1];
                b[2 * g + 1][0] = r[2]; b[2 * g + 1][1] = r[3];
            }
#pragma unroll
            for (int f = 0; f < 4; f++)
#pragma unroll
                for (int j = 0; j < 4; j++)
                    MMA16816(acc[f][j], a[f], b[j]);
        }
    }

    // ---- epilogue ----
#pragma unroll
    for (int f = 0; f < 4; f++) {
        const int row_lo = row0 + warp_m + f * 16 + (lane >> 2);
        const int row_hi = row_lo + 8;
        const bool ok_lo = row_lo < total;
        const bool ok_hi = row_hi < total;
#pragma unroll
        for (int j = 0; j < 4; j++) {
            const int col = c0 + warp_n + j * 8 + (lane & 3) * 2;
            if (OUT_HALF) {
                if (ok_lo)
                    *(__half2*)(OutH + (size_t)row_lo * HID + col) =
                        __floats2half2_rn(acc[f][j][0], acc[f][j][1]);
                if (ok_hi)
                    *(__half2*)(OutH + (size_t)row_hi * HID + col) =
                        __floats2half2_rn(acc[f][j][2], acc[f][j][3]);
            } else {
                float2 bb = *(const float2*)(bias + col);
                if (ok_lo)
                    *(float2*)(OutF + (size_t)row_lo * HID + col) =
                        make_float2(acc[f][j][0] + bb.x, acc[f][j][1] + bb.y);
                if (ok_hi)
                    *(float2*)(OutF + (size_t)row_hi * HID + col) =
                        make_float2(acc[f][j][2] + bb.x, acc[f][j][3] + bb.y);
            }
        }
    }
}

__global__ void __launch_bounds__(256, 2)
qkv_mma_kernel(const float* __restrict__ msg,
               const float* __restrict__ Wq,
               const float* __restrict__ Wk,
               const float* __restrict__ Wv,
               int total) {
    const int bx = blockIdx.x;            // 0..5, fastest -> X-tile L2 reuse
    const int mat = bx >> 1;
    const int c0 = (bx & 1) * 128;
    const float* W = (mat == 0) ? Wq : (mat == 1 ? Wk : Wv);
    __half* Out = (mat == 0) ? g_Qh : (mat == 1 ? g_Kh : g_Vh);
    gemm_body<false, true>(msg, nullptr, W, nullptr, Out, nullptr,
                           total, blockIdx.y * 128, c0);
}

__global__ void __launch_bounds__(256, 2)
proj_mma_kernel(const float* __restrict__ Wo,
                const float* __restrict__ bo,
                int total) {
    gemm_body<true, false>(nullptr, g_Oh, Wo, g_Y, nullptr, bo,
                           total, blockIdx.y * 128, blockIdx.x * 128);
}

// ================ Flash attention (HMMA, online softmax) ====================
// CTA = (mol, head); 4 warps x 32 query rows; 32-key chunks.
#define LDQ 72
#define LDK 72
#define LDVT 136
#define ATTN_SMEM ((128 * LDQ + 128 * LDK + 64 * LDVT) * 2)

__global__ void __launch_bounds__(128)
attn_mma_kernel(const int* __restrict__ b_starts,
                const int* __restrict__ b_sizes) {
    extern __shared__ __half ash[];
    __half* qS = ash;
    __half* kS = ash + 128 * LDQ;
    __half* vT = ash + 128 * LDQ + 128 * LDK;

    const int m = blockIdx.x;
    const int h = blockIdx.y;
    const int S = b_sizes[m];
    const int start = b_starts[m];
    const int tid = threadIdx.x;
    const int lane = tid & 31;
    const int wid = tid >> 5;

    // ---- stage Q, K (zero beyond S) ----
    {
        const int tok = tid;
        const bool ok = tok < S;
        const __half* qp = g_Qh + (size_t)(start + tok) * HID + h * DH;
        const __half* kp = g_Kh + (size_t)(start + tok) * HID + h * DH;
        const uint4 z = make_uint4(0, 0, 0, 0);
#pragma unroll
        for (int j = 0; j < 8; j++) {
            uint4 qv = ok ? ((const uint4*)qp)[j] : z;
            uint4 kv = ok ? ((const uint4*)kp)[j] : z;
            *(uint4*)(qS + tok * LDQ + j * 8) = qv;
            *(uint4*)(kS + tok * LDK + j * 8) = kv;
        }
    }
    // ---- stage V transposed: vT[d][token] ----
    {
        const int p = tid >> 1;            // token pair 0..63
        const int dh = (tid & 1) * 32;     // d offset
        const int t0 = 2 * p, t1 = 2 * p + 1;
        const __half* v0p = g_Vh + (size_t)(start + t0) * HID + h * DH + dh;
        const __half* v1p = g_Vh + (size_t)(start + t1) * HID + h * DH + dh;
        const uint4 z = make_uint4(0, 0, 0, 0);
        uint4 va[4], vb[4];
#pragma unroll
        for (int j = 0; j < 4; j++) {
            va[j] = (t0 < S) ? ((const uint4*)v0p)[j] : z;
            vb[j] = (t1 < S) ? ((const uint4*)v1p)[j] : z;
        }
        const __half* ahp = (const __half*)va;
        const __half* bhp = (const __half*)vb;
#pragma unroll
        for (int j = 0; j < 32; j++) {
            const int d = dh + j;
            *(__half2*)(vT + d * LDVT + t0) = __halves2half2(ahp[j], bhp[j]);
        }
    }
    __syncthreads();

    const uint32_t qBase = smem_u32(qS);
    const uint32_t kBase = smem_u32(kS);
    const uint32_t vBase = smem_u32(vT);
    const int wq0 = wid * 32;
    const uint32_t aOff = (uint32_t)(((lane & 15) * LDQ + (lane >> 4) * 8) * 2);
    const uint32_t bRow = (uint32_t)(((lane >> 4) << 3) + (lane & 7));
    const uint32_t bCol = (uint32_t)(((lane >> 3) & 1) * 8);

    // Q fragments: resident for whole kernel
    uint32_t qA[2][4][4];
#pragma unroll
    for (int f = 0; f < 2; f++)
#pragma unroll
        for (int kd = 0; kd < 4; kd++) {
            uint32_t addr = qBase +
                (uint32_t)(((wq0 + f * 16) * LDQ + kd * 16) * 2) + aOff;
            LDMX4(qA[f][kd], addr);
        }

    float oa[2][8][4];
#pragma unroll
    for (int f = 0; f < 2; f++)
#pragma unroll
        for (int dt = 0; dt < 8; dt++)
#pragma unroll
            for (int e = 0; e < 4; e++) oa[f][dt][e] = 0.f;
    float mx[2][2] = {{-3.0e38f, -3.0e38f}, {-3.0e38f, -3.0e38f}};
    float lsum[2][2] = {{0.f, 0.f}, {0.f, 0.f}};

    const int nchunks = (S + 31) >> 5;
    for (int ch = 0; ch < nchunks; ch++) {
        const int key0 = ch * 32;

        // ---- scores: Q @ K^T for this 32-key chunk ----
        float sacc[2][4][4];
#pragma unroll
        for (int f = 0; f < 2; f++)
#pragma unroll
            for (int n = 0; n < 4; n++)
#pragma unroll
                for (int e = 0; e < 4; e++) sacc[f][n][e] = 0.f;

#pragma unroll
        for (int kd = 0; kd < 4; kd++) {
            uint32_t bK[4][2];
#pragma unroll
            for (int g = 0; g < 2; g++) {
                uint32_t addr = kBase +
                    (uint32_t)(((key0 + g * 16 + bRow) * LDK + kd * 16 + bCol) * 2);
                uint32_t r[4];
                LDMX4(r, addr);
                bK[2 * g][0] = r[0]; bK[2 * g][1] = r[1];
                bK[2 * g + 1][0] = r[2]; bK[2 * g + 1][1] = r[3];
            }
#pragma unroll
            for (int f = 0; f < 2; f++)
#pragma unroll
                for (int n = 0; n < 4; n++)
                    MMA16816(sacc[f][n], qA[f][kd], bK[n]);
        }

        // ---- online softmax (per 2 rows owned by this thread) ----
        uint32_t pA[2][2][4];
#pragma unroll
        for (int f = 0; f < 2; f++) {
            float sv[4][4];
#pragma unroll
            for (int n = 0; n < 4; n++) {
                const int cb = key0 + n * 8 + (lane & 3) * 2;
                const bool k0ok = cb < S;
                const bool k1ok = (cb + 1) < S;
                sv[n][0] = k0ok ? sacc[f][n][0] * 0.125f : -1.0e30f;
                sv[n][1] = k1ok ? sacc[f][n][1] * 0.125f : -1.0e30f;
                sv[n][2] = k0ok ? sacc[f][n][2] * 0.125f : -1.0e30f;
                sv[n][3] = k1ok ? sacc[f][n][3] * 0.125f : -1.0e30f;
            }
            float m0 = -3.0e38f, m1 = -3.0e38f;
#pragma unroll
            for (int n = 0; n < 4; n++) {
                m0 = fmaxf(m0, fmaxf(sv[n][0], sv[n][1]));
                m1 = fmaxf(m1, fmaxf(sv[n][2], sv[n][3]));
            }
            m0 = fmaxf(m0, __shfl_xor_sync(0xffffffffu, m0, 1));
            m0 = fmaxf(m0, __shfl_xor_sync(0xffffffffu, m0, 2));
            m1 = fmaxf(m1, __shfl_xor_sync(0xffffffffu, m1, 1));
            m1 = fmaxf(m1, __shfl_xor_sync(0xffffffffu, m1, 2));
            const float nm0 = fmaxf(mx[f][0], m0);
            const float nm1 = fmaxf(mx[f][1], m1);
            const float sc0 = __expf(mx[f][0] - nm0);
            const float sc1 = __expf(mx[f][1] - nm1);
            mx[f][0] = nm0; mx[f][1] = nm1;

            float e[4][4];
            float s0 = 0.f, s1 = 0.f;
#pragma unroll
            for (int n = 0; n < 4; n++) {
                e[n][0] = __expf(sv[n][0] - nm0);
                e[n][1] = __expf(sv[n][1] - nm0);
                e[n][2] = __expf(sv[n][2] - nm1);
                e[n][3] = __expf(sv[n][3] - nm1);
                s0 += e[n][0] + e[n][1];
                s1 += e[n][2] + e[n][3];
            }
            s0 += __shfl_xor_sync(0xffffffffu, s0, 1);
            s0 += __shfl_xor_sync(0xffffffffu, s0, 2);
            s1 += __shfl_xor_sync(0xffffffffu, s1, 1);
            s1 += __shfl_xor_sync(0xffffffffu, s1, 2);
            lsum[f][0] = lsum[f][0] * sc0 + s0;
            lsum[f][1] = lsum[f][1] * sc1 + s1;

#pragma unroll
            for (int dt = 0; dt < 8; dt++) {
                oa[f][dt][0] *= sc0; oa[f][dt][1] *= sc0;
                oa[f][dt][2] *= sc1; oa[f][dt][3] *= sc1;
            }
#pragma unroll
            for (int kk = 0; kk < 2; kk++) {
                pA[f][kk][0] = h2u(__floats2half2_rn(e[2 * kk][0], e[2 * kk][1]));
                pA[f][kk][1] = h2u(__floats2half2_rn(e[2 * kk][2], e[2 * kk][3]));
                pA[f][kk][2] = h2u(__floats2half2_rn(e[2 * kk + 1][0], e[2 * kk + 1][1]));
                pA[f][kk][3] = h2u(__floats2half2_rn(e[2 * kk + 1][2], e[2 * kk + 1][3]));
            }
        }

        // ---- O += P @ V ----
#pragma unroll
        for (int kk = 0; kk < 2; kk++) {
            uint32_t bV[8][2];
#pragma unroll
            for (int g = 0; g < 4; g++) {
                uint32_t addr = vBase +
                    (uint32_t)(((g * 16 + bRow) * LDVT + key0 + kk * 16 + bCol) * 2);
                uint32_t r[4];
                LDMX4(r, addr);
                bV[2 * g][0] = r[0]; bV[2 * g][1] = r[1];
                bV[2 * g + 1][0] = r[2]; bV[2 * g + 1][1] = r[3];
            }
#pragma unroll
            for (int f = 0; f < 2; f++)
#pragma unroll
                for (int dt = 0; dt < 8; dt++)
                    MMA16816(oa[f][dt], pA[f][kk], bV[dt]);
        }
    }

    // ---- store: ReLU(o / l) -> g_Oh ----
#pragma unroll
    for (int f = 0; f < 2; f++) {
        const float i0 = 1.0f / lsum[f][0];
        const float i1 = 1.0f / lsum[f][1];
        const int r = wq0 + f * 16 + (lane >> 2);
        const bool ok0 = r < S;
        const bool ok1 = (r + 8) < S;
#pragma unroll
        for (int dt = 0; dt < 8; dt++) {
            const int c = h * DH + dt * 8 + (lane & 3) * 2;
            if (ok0)
                *(__half2*)(g_Oh + (size_t)(start + r) * HID + c) =
                    __floats2half2_rn(fmaxf(oa[f][dt][0] * i0, 0.f),
                                      fmaxf(oa[f][dt][1] * i0, 0.f));
            if (ok1)
                *(__half2*)(g_Oh + (size_t)(start + r + 8) * HID + c) =
                    __floats2half2_rn(fmaxf(oa[f][dt][2] * i1, 0.f),
                                      fmaxf(oa[f][dt][3] * i1, 0.f));
        }
    }
}

// ======================= LayerNorm ==========================================
__global__ void __launch_bounds__(256)
ln_kernel(const float* __restrict__ gamma,
          const float* __restrict__ beta,
          float* __restrict__ out,
          int total) {
    const int row = blockIdx.x * 8 + (threadIdx.x >> 5);
    if (row >= total) return;
    const int lane = threadIdx.x & 31;

    const float* y = g_Y + (size_t)row * HID;
    float4 v0 = *(const float4*)(y + lane * 4);
    float4 v1 = *(const float4*)(y + 128 + lane * 4);

    float s = v0.x + v0.y + v0.z + v0.w + v1.x + v1.y + v1.z + v1.w;
#pragma unroll
    for (int off = 16; off > 0; off >>= 1) s += __shfl_xor_sync(0xffffffffu, s, off);
    float mu = s * (1.f / 256.f);

    float q = 0.f;
    {
        float d;
        d = v0.x - mu; q += d * d; d = v0.y - mu; q += d * d;
        d = v0.z - mu; q += d * d; d = v0.w - mu; q += d * d;
        d = v1.x - mu; q += d * d; d = v1.y - mu; q += d * d;
        d = v1.z - mu; q += d * d; d = v1.w - mu; q += d * d;
    }
#pragma unroll
    for (int off = 16; off > 0; off >>= 1) q += __shfl_xor_sync(0xffffffffu, q, off);
    float rsig = rsqrtf(q * (1.f / 256.f) + 1e-5f);

    float* op = out + (size_t)row * HID;
    if (row == 0) {
        *(float4*)(op + lane * 4) = make_float4(0.f, 0.f, 0.f, 0.f);
        *(float4*)(op + 128 + lane * 4) = make_float4(0.f, 0.f, 0.f, 0.f);
    } else {
        float4 g0 = *(const float4*)(gamma + lane * 4);
        float4 g1 = *(const float4*)(gamma + 128 + lane * 4);
        float4 b0 = *(const float4*)(beta + lane * 4);
        float4 b1 = *(const float4*)(beta + 128 + lane * 4);
        float4 r0 = make_float4((v0.x - mu) * rsig * g0.x + b0.x,
                                (v0.y - mu) * rsig * g0.y + b0.y,
                                (v0.z - mu) * rsig * g0.z + b0.z,
                                (v0.w - mu) * rsig * g0.w + b0.w);
        float4 r1 = make_float4((v1.x - mu) * rsig * g1.x + b1.x,
                                (v1.y - mu) * rsig * g1.y + b1.y,
                                (v1.z - mu) * rsig * g1.z + b1.z,
                                (v1.w - mu) * rsig * g1.w + b1.w);
        *(float4*)(op + lane * 4) = r0;
        *(float4*)(op + 128 + lane * 4) = r1;
    }
}

// ---------------------------------------------------------------------------
extern "C" void kernel_launch(void* const* d_in, const int* in_sizes, int n_in,
                              void* d_out, int out_size) {
    const float* msg      = (const float*)d_in[0];
    const float* Wq       = (const float*)d_in[1];
    const float* Wk       = (const float*)d_in[2];
    const float* Wv       = (const float*)d_in[3];
    const float* Wo       = (const float*)d_in[4];
    const float* bo       = (const float*)d_in[5];
    const float* gamma    = (const float*)d_in[6];
    const float* beta     = (const float*)d_in[7];
    const int*   b_starts = (const int*)d_in[8];
    const int*   b_sizes  = (const int*)d_in[9];
    float* out = (float*)d_out;

    const int total = in_sizes[0] / HID;
    const int tiles = (total + 127) / 128;

    cudaFuncSetAttribute(qkv_mma_kernel,
                         cudaFuncAttributeMaxDynamicSharedMemorySize, GEMM_SMEM);
    cudaFuncSetAttribute(proj_mma_kernel,
                         cudaFuncAttributeMaxDynamicSharedMemorySize, GEMM_SMEM);
    cudaFuncSetAttribute(attn_mma_kernel,
                         cudaFuncAttributeMaxDynamicSharedMemorySize, ATTN_SMEM);

    dim3 ga(6, tiles);
    qkv_mma_kernel<<<ga, 256, GEMM_SMEM>>>(msg, Wq, Wk, Wv, total);

    dim3 gb(N_MOLS, NH);
    attn_mma_kernel<<<gb, 128, ATTN_SMEM>>>(b_starts, b_sizes);

    dim3 gc(2, tiles);
    proj_mma_kernel<<<gc, 256, GEMM_SMEM>>>(Wo, bo, total);

    ln_kernel<<<(total + 7) / 8, 256>>>(gamma, beta, out, total);
}

// round 10
// speedup vs baseline: 8.1092x; 1.5333x over previous
#include <cuda_runtime.h>
#include <cuda_fp16.h>
#include <cstdint>

#define HID 256
#define NH 4
#define DH 64
#define N_MOLS 2048
#define MAX_LEN 128
#define MAX_TOTAL (1 + N_MOLS * MAX_LEN)

// Scratch (device globals: allocation-free rule). Zero-initialized at load.
__device__ unsigned short g_Xh_u[(size_t)MAX_TOTAL * HID];   // msg fp16
__device__ unsigned short g_Qh_u[(size_t)MAX_TOTAL * HID];
__device__ unsigned short g_Kh_u[(size_t)MAX_TOTAL * HID];
__device__ unsigned short g_Vh_u[(size_t)MAX_TOTAL * HID];
__device__ unsigned short g_Oh_u[(size_t)MAX_TOTAL * HID];
__device__ unsigned short g_Wh_u[4 * HID * HID];             // Wq,Wk,Wv,Wo fp16

#define g_Xh ((__half*)g_Xh_u)
#define g_Qh ((__half*)g_Qh_u)
#define g_Kh ((__half*)g_Kh_u)
#define g_Vh ((__half*)g_Vh_u)
#define g_Oh ((__half*)g_Oh_u)
#define g_Wh ((__half*)g_Wh_u)

// ============================ helpers =======================================
__device__ __forceinline__ uint32_t smem_u32(const void* p) {
    uint32_t a;
    asm("{ .reg .u64 t; cvta.to.shared.u64 t, %1; cvt.u32.u64 %0, t; }"
        : "=r"(a) : "l"(p));
    return a;
}
__device__ __forceinline__ uint32_t h2u(__half2 h) {
    return *reinterpret_cast<uint32_t*>(&h);
}
__device__ __forceinline__ uint4 cvt8(float4 v0, float4 v1) {
    uint4 w;
    w.x = h2u(__floats2half2_rn(v0.x, v0.y));
    w.y = h2u(__floats2half2_rn(v0.z, v0.w));
    w.z = h2u(__floats2half2_rn(v1.x, v1.y));
    w.w = h2u(__floats2half2_rn(v1.z, v1.w));
    return w;
}

#define CP16(dst, src) \
    asm volatile("cp.async.cg.shared.global [%0], [%1], 16;" \
                 :: "r"(dst), "l"(src) : "memory")
#define CP_COMMIT_WAIT \
    asm volatile("cp.async.commit_group;\n\tcp.async.wait_group 0;" ::: "memory")

#define LDMX4(r, addr) \
    asm volatile("ldmatrix.sync.aligned.m8n8.x4.shared.b16 {%0,%1,%2,%3}, [%4];" \
                 : "=r"((r)[0]), "=r"((r)[1]), "=r"((r)[2]), "=r"((r)[3]) \
                 : "r"(addr))

#define MMA16816(d, a, b) \
    asm volatile("mma.sync.aligned.m16n8k16.row.col.f32.f16.f16.f32 " \
                 "{%0,%1,%2,%3}, {%4,%5,%6,%7}, {%8,%9}, {%0,%1,%2,%3};" \
                 : "+f"((d)[0]), "+f"((d)[1]), "+f"((d)[2]), "+f"((d)[3]) \
                 : "r"((a)[0]), "r"((a)[1]), "r"((a)[2]), "r"((a)[3]), \
                   "r"((b)[0]), "r"((b)[1]))

// ======================= conversion kernels =================================
__global__ void __launch_bounds__(512)
cvt_msg_kernel(const float* __restrict__ msg, int total) {
    const int idx = blockIdx.x * 512 + threadIdx.x;   // one per 8 floats
    const int n = total * (HID / 8);
    if (idx >= n) return;
    const float4* p = (const float4*)msg + (size_t)idx * 2;
    ((uint4*)g_Xh)[idx] = cvt8(p[0], p[1]);
}

__global__ void __launch_bounds__(256)
cvt_w_kernel(const float* __restrict__ Wq, const float* __restrict__ Wk,
             const float* __restrict__ Wv, const float* __restrict__ Wo) {
    const int idx = blockIdx.x * 256 + threadIdx.x;   // 4*8192 groups of 8
    const int mat = idx >> 13;
    const int off = idx & 8191;
    const float* W = (mat == 0) ? Wq : (mat == 1 ? Wk : (mat == 2 ? Wv : Wo));
    const float4* p = (const float4*)W + (size_t)off * 2;
    ((uint4*)(g_Wh + mat * HID * HID))[off] = cvt8(p[0], p[1]);
}

// ======================= QKV GEMM (fp16 in, fp16 out) =======================
// Out[r][c] = sum_k X[r][k] * W[c][k]; 128x128 tile, 256 thr, warp 64x32.
#define LDA 136
#define GEMM_SMEM (2 * 128 * LDA * 2)

__global__ void __launch_bounds__(256, 2)
qkv_mma_kernel(int total) {
    extern __shared__ __half sh[];
    __half* sA = sh;
    __half* sB = sh + 128 * LDA;

    const int bx = blockIdx.x;            // 0..5 fastest -> X-tile L2 reuse
    const int mat = bx >> 1;
    const int c0 = (bx & 1) * 128;
    const __half* __restrict__ Ah = g_Xh;
    const __half* __restrict__ Wh = g_Wh + mat * HID * HID;
    __half* __restrict__ OutH = (mat == 0) ? g_Qh : (mat == 1 ? g_Kh : g_Vh);
    const int row0 = blockIdx.y * 128;

    const int tid = threadIdx.x;
    const int lane = tid & 31;
    const int wid = tid >> 5;

    float acc[4][4][4];
#pragma unroll
    for (int f = 0; f < 4; f++)
#pragma unroll
        for (int j = 0; j < 4; j++)
#pragma unroll
            for (int e = 0; e < 4; e++) acc[f][j][e] = 0.f;

    const int srow = tid >> 1;
    const int sseg = tid & 1;
    const uint32_t aBase = smem_u32(sA);
    const uint32_t bBase = smem_u32(sB);
    const uint32_t dA = aBase + (uint32_t)((srow * LDA + sseg * 64) * 2);
    const uint32_t dB = bBase + (uint32_t)((srow * LDA + sseg * 64) * 2);
    const __half* srcA = Ah + (size_t)(row0 + srow) * HID + sseg * 64;
    const __half* srcB = Wh + (size_t)(c0 + srow) * HID + sseg * 64;

    const int warp_m = (wid >> 2) * 64;
    const int warp_n = (wid & 3) * 32;
    const uint32_t aOff = (uint32_t)(((lane & 15) * LDA + (lane >> 4) * 8) * 2);
    const uint32_t bRow = (uint32_t)(((lane >> 4) << 3) + (lane & 7));
    const uint32_t bCol = (uint32_t)(((lane >> 3) & 1) * 8);

#pragma unroll
    for (int kc = 0; kc < 2; kc++) {
        const int k0 = kc * 128;
        if (kc) __syncthreads();
#pragma unroll
        for (int j = 0; j < 8; j++) {        // 64 halves = 8 x 16B
            CP16(dA + j * 16, srcA + k0 + j * 8);
            CP16(dB + j * 16, srcB + k0 + j * 8);
        }
        CP_COMMIT_WAIT;
        __syncthreads();

#pragma unroll
        for (int ks = 0; ks < 8; ks++) {
            uint32_t a[4][4];
            uint32_t b[4][2];
#pragma unroll
            for (int f = 0; f < 4; f++) {
                uint32_t addr = aBase +
                    (uint32_t)(((warp_m + f * 16) * LDA + ks * 16) * 2) + aOff;
                LDMX4(a[f], addr);
            }
#pragma unroll
            for (int g = 0; g < 2; g++) {
                uint32_t addr = bBase +
                    (uint32_t)(((warp_n + g * 16 + bRow) * LDA +
                                ks * 16 + bCol) * 2);
                uint32_t r[4];
                LDMX4(r, addr);
                b[2 * g][0] = r[0]; b[2 * g][1] = r[1];
                b[2 * g + 1][0] = r[2]; b[2 * g + 1][1] = r[3];
            }
#pragma unroll
            for (int f = 0; f < 4; f++)
#pragma unroll
                for (int j = 0; j < 4; j++)
                    MMA16816(acc[f][j], a[f], b[j]);
        }
    }

#pragma unroll
    for (int f = 0; f < 4; f++) {
        const int row_lo = row0 + warp_m + f * 16 + (lane >> 2);
        const int row_hi = row_lo + 8;
#pragma unroll
        for (int j = 0; j < 4; j++) {
            const int col = c0 + warp_n + j * 8 + (lane & 3) * 2;
            if (row_lo < total)
                *(__half2*)(OutH + (size_t)row_lo * HID + col) =
                    __floats2half2_rn(acc[f][j][0], acc[f][j][1]);
            if (row_hi < total)
                *(__half2*)(OutH + (size_t)row_hi * HID + col) =
                    __floats2half2_rn(acc[f][j][2], acc[f][j][3]);
        }
    }
}

// ================ Flash attention (HMMA, online softmax) ====================
#define LDQ 72
#define LDK 72
#define LDVT 136
#define ATTN_SMEM ((128 * LDQ + 128 * LDK + 64 * LDVT) * 2)

__global__ void __launch_bounds__(128)
attn_mma_kernel(const int* __restrict__ b_starts,
                const int* __restrict__ b_sizes) {
    extern __shared__ __half ash[];
    __half* qS = ash;
    __half* kS = ash + 128 * LDQ;
    __half* vT = ash + 128 * LDQ + 128 * LDK;

    const int m = blockIdx.x;
    const int h = blockIdx.y;
    const int S = b_sizes[m];
    const int start = b_starts[m];
    const int tid = threadIdx.x;
    const int lane = tid & 31;
    const int wid = tid >> 5;

    // ---- stage Q, K (zero beyond S) ----
    {
        const int tok = tid;
        const bool ok = tok < S;
        const __half* qp = g_Qh + (size_t)(start + tok) * HID + h * DH;
        const __half* kp = g_Kh + (size_t)(start + tok) * HID + h * DH;
        const uint4 z = make_uint4(0, 0, 0, 0);
#pragma unroll
        for (int j = 0; j < 8; j++) {
            uint4 qv = ok ? ((const uint4*)qp)[j] : z;
            uint4 kv = ok ? ((const uint4*)kp)[j] : z;
            *(uint4*)(qS + tok * LDQ + j * 8) = qv;
            *(uint4*)(kS + tok * LDK + j * 8) = kv;
        }
    }
    // ---- stage V transposed: vT[d][token] ----
    {
        const int p = tid >> 1;
        const int dh = (tid & 1) * 32;
        const int t0 = 2 * p, t1 = 2 * p + 1;
        const __half* v0p = g_Vh + (size_t)(start + t0) * HID + h * DH + dh;
        const __half* v1p = g_Vh + (size_t)(start + t1) * HID + h * DH + dh;
        const uint4 z = make_uint4(0, 0, 0, 0);
        uint4 va[4], vb[4];
#pragma unroll
        for (int j = 0; j < 4; j++) {
            va[j] = (t0 < S) ? ((const uint4*)v0p)[j] : z;
            vb[j] = (t1 < S) ? ((const uint4*)v1p)[j] : z;
        }
        const __half* ahp = (const __half*)va;
        const __half* bhp = (const __half*)vb;
#pragma unroll
        for (int j = 0; j < 32; j++) {
            const int d = dh + j;
            *(__half2*)(vT + d * LDVT + t0) = __halves2half2(ahp[j], bhp[j]);
        }
    }
    __syncthreads();

    const int wq0 = wid * 32;
    if (wq0 >= S) return;   // idle query warps exit (no more barriers below)

    const uint32_t qBase = smem_u32(qS);
    const uint32_t kBase = smem_u32(kS);
    const uint32_t vBase = smem_u32(vT);
    const uint32_t aOff = (uint32_t)(((lane & 15) * LDQ + (lane >> 4) * 8) * 2);
    const uint32_t bRow = (uint32_t)(((lane >> 4) << 3) + (lane & 7));
    const uint32_t bCol = (uint32_t)(((lane >> 3) & 1) * 8);

    uint32_t qA[2][4][4];
#pragma unroll
    for (int f = 0; f < 2; f++)
#pragma unroll
        for (int kd = 0; kd < 4; kd++) {
            uint32_t addr = qBase +
                (uint32_t)(((wq0 + f * 16) * LDQ + kd * 16) * 2) + aOff;
            LDMX4(qA[f][kd], addr);
        }

    float oa[2][8][4];
#pragma unroll
    for (int f = 0; f < 2; f++)
#pragma unroll
        for (int dt = 0; dt < 8; dt++)
#pragma unroll
            for (int e = 0; e < 4; e++) oa[f][dt][e] = 0.f;
    float mx[2][2] = {{-3.0e38f, -3.0e38f}, {-3.0e38f, -3.0e38f}};
    float lsum[2][2] = {{0.f, 0.f}, {0.f, 0.f}};

    const int nchunks = (S + 31) >> 5;
    for (int ch = 0; ch < nchunks; ch++) {
        const int key0 = ch * 32;

        float sacc[2][4][4];
#pragma unroll
        for (int f = 0; f < 2; f++)
#pragma unroll
            for (int n = 0; n < 4; n++)
#pragma unroll
                for (int e = 0; e < 4; e++) sacc[f][n][e] = 0.f;

#pragma unroll
        for (int kd = 0; kd < 4; kd++) {
            uint32_t bK[4][2];
#pragma unroll
            for (int g = 0; g < 2; g++) {
                uint32_t addr = kBase +
                    (uint32_t)(((key0 + g * 16 + bRow) * LDK + kd * 16 + bCol) * 2);
                uint32_t r[4];
                LDMX4(r, addr);
                bK[2 * g][0] = r[0]; bK[2 * g][1] = r[1];
                bK[2 * g + 1][0] = r[2]; bK[2 * g + 1][1] = r[3];
            }
#pragma unroll
            for (int f = 0; f < 2; f++)
#pragma unroll
                for (int n = 0; n < 4; n++)
                    MMA16816(sacc[f][n], qA[f][kd], bK[n]);
        }

        uint32_t pA[2][2][4];
#pragma unroll
        for (int f = 0; f < 2; f++) {
            float sv[4][4];
#pragma unroll
            for (int n = 0; n < 4; n++) {
                const int cb = key0 + n * 8 + (lane & 3) * 2;
                const bool k0ok = cb < S;
                const bool k1ok = (cb + 1) < S;
                sv[n][0] = k0ok ? sacc[f][n][0] * 0.125f : -1.0e30f;
                sv[n][1] = k1ok ? sacc[f][n][1] * 0.125f : -1.0e30f;
                sv[n][2] = k0ok ? sacc[f][n][2] * 0.125f : -1.0e30f;
                sv[n][3] = k1ok ? sacc[f][n][3] * 0.125f : -1.0e30f;
            }
            float m0 = -3.0e38f, m1 = -3.0e38f;
#pragma unroll
            for (int n = 0; n < 4; n++) {
                m0 = fmaxf(m0, fmaxf(sv[n][0], sv[n][1]));
                m1 = fmaxf(m1, fmaxf(sv[n][2], sv[n][3]));
            }
            m0 = fmaxf(m0, __shfl_xor_sync(0xffffffffu, m0, 1));
            m0 = fmaxf(m0, __shfl_xor_sync(0xffffffffu, m0, 2));
            m1 = fmaxf(m1, __shfl_xor_sync(0xffffffffu, m1, 1));
            m1 = fmaxf(m1, __shfl_xor_sync(0xffffffffu, m1, 2));
            const float nm0 = fmaxf(mx[f][0], m0);
            const float nm1 = fmaxf(mx[f][1], m1);
            const float sc0 = __expf(mx[f][0] - nm0);
            const float sc1 = __expf(mx[f][1] - nm1);
            mx[f][0] = nm0; mx[f][1] = nm1;

            float e[4][4];
            float s0 = 0.f, s1 = 0.f;
#pragma unroll
            for (int n = 0; n < 4; n++) {
                e[n][0] = __expf(sv[n][0] - nm0);
                e[n][1] = __expf(sv[n][1] - nm0);
                e[n][2] = __expf(sv[n][2] - nm1);
                e[n][3] = __expf(sv[n][3] - nm1);
                s0 += e[n][0] + e[n][1];
                s1 += e[n][2] + e[n][3];
            }
            s0 += __shfl_xor_sync(0xffffffffu, s0, 1);
            s0 += __shfl_xor_sync(0xffffffffu, s0, 2);
            s1 += __shfl_xor_sync(0xffffffffu, s1, 1);
            s1 += __shfl_xor_sync(0xffffffffu, s1, 2);
            lsum[f][0] = lsum[f][0] * sc0 + s0;
            lsum[f][1] = lsum[f][1] * sc1 + s1;

#pragma unroll
            for (int dt = 0; dt < 8; dt++) {
                oa[f][dt][0] *= sc0; oa[f][dt][1] *= sc0;
                oa[f][dt][2] *= sc1; oa[f][dt][3] *= sc1;
            }
#pragma unroll
            for (int kk = 0; kk < 2; kk++) {
                pA[f][kk][0] = h2u(__floats2half2_rn(e[2 * kk][0], e[2 * kk][1]));
                pA[f][kk][1] = h2u(__floats2half2_rn(e[2 * kk][2], e[2 * kk][3]));
                pA[f][kk][2] = h2u(__floats2half2_rn(e[2 * kk + 1][0], e[2 * kk + 1][1]));
                pA[f][kk][3] = h2u(__floats2half2_rn(e[2 * kk + 1][2], e[2 * kk + 1][3]));
            }
        }

#pragma unroll
        for (int kk = 0; kk < 2; kk++) {
            uint32_t bV[8][2];
#pragma unroll
            for (int g = 0; g < 4; g++) {
                uint32_t addr = vBase +
                    (uint32_t)(((g * 16 + bRow) * LDVT + key0 + kk * 16 + bCol) * 2);
                uint32_t r[4];
                LDMX4(r, addr);
                bV[2 * g][0] = r[0]; bV[2 * g][1] = r[1];
                bV[2 * g + 1][0] = r[2]; bV[2 * g + 1][1] = r[3];
            }
#pragma unroll
            for (int f = 0; f < 2; f++)
#pragma unroll
                for (int dt = 0; dt < 8; dt++)
                    MMA16816(oa[f][dt], pA[f][kk], bV[dt]);
        }
    }

#pragma unroll
    for (int f = 0; f < 2; f++) {
        const float i0 = 1.0f / lsum[f][0];
        const float i1 = 1.0f / lsum[f][1];
        const int r = wq0 + f * 16 + (lane >> 2);
        const bool ok0 = r < S;
        const bool ok1 = (r + 8) < S;
#pragma unroll
        for (int dt = 0; dt < 8; dt++) {
            const int c = h * DH + dt * 8 + (lane & 3) * 2;
            if (ok0)
                *(__half2*)(g_Oh + (size_t)(start + r) * HID + c) =
                    __floats2half2_rn(fmaxf(oa[f][dt][0] * i0, 0.f),
                                      fmaxf(oa[f][dt][1] * i0, 0.f));
            if (ok1)
                *(__half2*)(g_Oh + (size_t)(start + r + 8) * HID + c) =
                    __floats2half2_rn(fmaxf(oa[f][dt][2] * i1, 0.f),
                                      fmaxf(oa[f][dt][3] * i1, 0.f));
        }
    }
}

// ============== Output projection + fused LayerNorm =========================
// 512 threads, 16 warps (4m x 4n), warp tile 32x64, BN=256 (full row / CTA).
#define PLN_HALVES ((128 + 256) * LDA)
#define PROJ_SMEM (PLN_HALVES * 2 + 4 * 128 * 2 * 4)

__global__ void __launch_bounds__(512, 1)
proj_ln_kernel(const float* __restrict__ bo,
               const float* __restrict__ gamma,
               const float* __restrict__ beta,
               float* __restrict__ out,
               int total) {
    extern __shared__ __half sh[];
    __half* sA = sh;                       // [128][LDA]
    __half* sB = sh + 128 * LDA;           // [256][LDA]
    float* rsum = (float*)(sh + PLN_HALVES);   // [4][128]
    float* rsq  = rsum + 4 * 128;              // [4][128]

    const int row0 = blockIdx.x * 128;
    const int tid = threadIdx.x;
    const int lane = tid & 31;
    const int wid = tid >> 5;
    const __half* __restrict__ Wo16 = g_Wh + 3 * HID * HID;

    float acc[2][8][4];
#pragma unroll
    for (int f = 0; f < 2; f++)
#pragma unroll
        for (int j = 0; j < 8; j++)
#pragma unroll
            for (int e = 0; e < 4; e++) acc[f][j][e] = 0.f;

    const uint32_t aBase = smem_u32(sA);
    const uint32_t bBase = smem_u32(sB);
    // A staging: thread -> row tid>>2, seg tid&3 (32 halves = 4 x 16B)
    const int arow = tid >> 2, aseg = tid & 3;
    const uint32_t dA = aBase + (uint32_t)((arow * LDA + aseg * 32) * 2);
    const __half* srcA = g_Oh + (size_t)(row0 + arow) * HID + aseg * 32;
    // B staging: thread -> row tid>>1, seg tid&1 (64 halves = 8 x 16B)
    const int brow = tid >> 1, bseg = tid & 1;
    const uint32_t dB = bBase + (uint32_t)((brow * LDA + bseg * 64) * 2);
    const __half* srcB = Wo16 + (size_t)brow * HID + bseg * 64;

    const int warp_m = (wid >> 2) * 32;
    const int warp_n = (wid & 3) * 64;
    const uint32_t aOff = (uint32_t)(((lane & 15) * LDA + (lane >> 4) * 8) * 2);
    const uint32_t bRow = (uint32_t)(((lane >> 4) << 3) + (lane & 7));
    const uint32_t bCol = (uint32_t)(((lane >> 3) & 1) * 8);

#pragma unroll
    for (int kc = 0; kc < 2; kc++) {
        const int k0 = kc * 128;
        if (kc) __syncthreads();
#pragma unroll
        for (int j = 0; j < 4; j++)          // 32 halves = 4 x 16B
            CP16(dA + j * 16, srcA + k0 + j * 8);
#pragma unroll
        for (int j = 0; j < 8; j++)          // 64 halves = 8 x 16B
            CP16(dB + j * 16, srcB + k0 + j * 8);
        CP_COMMIT_WAIT;
        __syncthreads();

#pragma unroll
        for (int ks = 0; ks < 8; ks++) {
            uint32_t a[2][4];
            uint32_t b[8][2];
#pragma unroll
            for (int f = 0; f < 2; f++) {
                uint32_t addr = aBase +
                    (uint32_t)(((warp_m + f * 16) * LDA + ks * 16) * 2) + aOff;
                LDMX4(a[f], addr);
            }
#pragma unroll
            for (int g = 0; g < 4; g++) {
                uint32_t addr = bBase +
                    (uint32_t)(((warp_n + g * 16 + bRow) * LDA +
                                ks * 16 + bCol) * 2);
                uint32_t r[4];
                LDMX4(r, addr);
                b[2 * g][0] = r[0]; b[2 * g][1] = r[1];
                b[2 * g + 1][0] = r[2]; b[2 * g + 1][1] = r[3];
            }
#pragma unroll
            for (int f = 0; f < 2; f++)
#pragma unroll
                for (int j = 0; j < 8; j++)
                    MMA16816(acc[f][j], a[f], b[j]);
        }
    }

    // ---- bias add + per-row partial sums ----
#pragma unroll
    for (int f = 0; f < 2; f++) {
        float sl = 0.f, ql = 0.f, shg = 0.f, qh = 0.f;
#pragma unroll
        for (int j = 0; j < 8; j++) {
            const int col = warp_n + j * 8 + (lane & 3) * 2;
            float2 bb = *(const float2*)(bo + col);
            acc[f][j][0] += bb.x; acc[f][j][1] += bb.y;
            acc[f][j][2] += bb.x; acc[f][j][3] += bb.y;
            sl += acc[f][j][0] + acc[f][j][1];
            ql += acc[f][j][0] * acc[f][j][0] + acc[f][j][1] * acc[f][j][1];
            shg += acc[f][j][2] + acc[f][j][3];
            qh += acc[f][j][2] * acc[f][j][2] + acc[f][j][3] * acc[f][j][3];
        }
        sl += __shfl_xor_sync(0xffffffffu, sl, 1);
        sl += __shfl_xor_sync(0xffffffffu, sl, 2);
        ql += __shfl_xor_sync(0xffffffffu, ql, 1);
        ql += __shfl_xor_sync(0xffffffffu, ql, 2);
        shg += __shfl_xor_sync(0xffffffffu, shg, 1);
        shg += __shfl_xor_sync(0xffffffffu, shg, 2);
        qh += __shfl_xor_sync(0xffffffffu, qh, 1);
        qh += __shfl_xor_sync(0xffffffffu, qh, 2);
        if ((lane & 3) == 0) {
            const int nw = wid & 3;
            const int rlo = warp_m + f * 16 + (lane >> 2);
            rsum[nw * 128 + rlo] = sl;
            rsq[nw * 128 + rlo] = ql;
            rsum[nw * 128 + rlo + 8] = shg;
            rsq[nw * 128 + rlo + 8] = qh;
        }
    }
    __syncthreads();

    // ---- LN + store ----
#pragma unroll
    for (int f = 0; f < 2; f++) {
        const int rlo = warp_m + f * 16 + (lane >> 2);
        const int rhi = rlo + 8;
        float s0 = rsum[rlo] + rsum[128 + rlo] + rsum[256 + rlo] + rsum[384 + rlo];
        float q0 = rsq[rlo] + rsq[128 + rlo] + rsq[256 + rlo] + rsq[384 + rlo];
        float s1 = rsum[rhi] + rsum[128 + rhi] + rsum[256 + rhi] + rsum[384 + rhi];
        float q1 = rsq[rhi] + rsq[128 + rhi] + rsq[256 + rhi] + rsq[384 + rhi];
        const float mu0 = s0 * (1.f / 256.f);
        const float mu1 = s1 * (1.f / 256.f);
        const float rs0 = rsqrtf(fmaxf(q0 * (1.f / 256.f) - mu0 * mu0, 0.f) + 1e-5f);
        const float rs1 = rsqrtf(fmaxf(q1 * (1.f / 256.f) - mu1 * mu1, 0.f) + 1e-5f);
        const int g_lo = row0 + rlo;
        const int g_hi = row0 + rhi;
        const bool ok0 = g_lo < total;
        const bool ok1 = g_hi < total;
        const bool z0 = (g_lo == 0);
#pragma unroll
        for (int j = 0; j < 8; j++) {
            const int col = warp_n + j * 8 + (lane & 3) * 2;
            float2 gg = *(const float2*)(gamma + col);
            float2 be = *(const float2*)(beta + col);
            if (ok0) {
                float2 v;
                if (z0) { v.x = 0.f; v.y = 0.f; }
                else {
                    v.x = (acc[f][j][0] - mu0) * rs0 * gg.x + be.x;
                    v.y = (acc[f][j][1] - mu0) * rs0 * gg.y + be.y;
                }
                *(float2*)(out + (size_t)g_lo * HID + col) = v;
            }
            if (ok1) {
                float2 v;
                v.x = (acc[f][j][2] - mu1) * rs1 * gg.x + be.x;
                v.y = (acc[f][j][3] - mu1) * rs1 * gg.y + be.y;
                *(float2*)(out + (size_t)g_hi * HID + col) = v;
            }
        }
    }
}

// ---------------------------------------------------------------------------
extern "C" void kernel_launch(void* const* d_in, const int* in_sizes, int n_in,
                              void* d_out, int out_size) {
    const float* msg      = (const float*)d_in[0];
    const float* Wq       = (const float*)d_in[1];
    const float* Wk       = (const float*)d_in[2];
    const float* Wv       = (const float*)d_in[3];
    const float* Wo       = (const float*)d_in[4];
    const float* bo       = (const float*)d_in[5];
    const float* gamma    = (const float*)d_in[6];
    const float* beta     = (const float*)d_in[7];
    const int*   b_starts = (const int*)d_in[8];
    const int*   b_sizes  = (const int*)d_in[9];
    float* out = (float*)d_out;

    const int total = in_sizes[0] / HID;
    const int tiles = (total + 127) / 128;

    cudaFuncSetAttribute(qkv_mma_kernel,
                         cudaFuncAttributeMaxDynamicSharedMemorySize, GEMM_SMEM);
    cudaFuncSetAttribute(attn_mma_kernel,
                         cudaFuncAttributeMaxDynamicSharedMemorySize, ATTN_SMEM);
    cudaFuncSetAttribute(proj_ln_kernel,
                         cudaFuncAttributeMaxDynamicSharedMemorySize, PROJ_SMEM);

    cvt_msg_kernel<<<(total * (HID / 8) + 511) / 512, 512>>>(msg, total);
    cvt_w_kernel<<<128, 256>>>(Wq, Wk, Wv, Wo);

    dim3 ga(6, tiles);
    qkv_mma_kernel<<<ga, 256, GEMM_SMEM>>>(total);

    dim3 gb(N_MOLS, NH);
    attn_mma_kernel<<<gb, 128, ATTN_SMEM>>>(b_starts, b_sizes);

    proj_ln_kernel<<<tiles, 512, PROJ_SMEM>>>(bo, gamma, beta, out, total);
}